// round 1
// baseline (speedup 1.0000x reference)
#include <cuda_runtime.h>
#include <math.h>

#define B_ 16
#define D_ 37
#define F_ 4096
#define I_ 64

// ---- scratch (static device globals: allocation-free) ----
__device__ float g_qT[B_ * I_ * F_];              // [b][i][f], LN'd, pre-scaled by 1/8
__device__ float g_kT[B_ * I_ * F_];              // [b][i][f], LN'd
__device__ float g_v [B_ * F_ * I_];              // [b][f][i], LN'd
__device__ float g_rc[B_ * F_];                   // 1 / column-sum per key
__device__ float g_S [268435456];                 // 16*4096*4096: S^T = [b][key n][query m]

// ---------------------------------------------------------------------------
// Kernel 1: q/k/v = LN(x^T @ W) ; q pre-scaled by 1/sqrt(64); q,k stored
// transposed [b][i][f] so the big GEMM needs no smem transpose.
// One warp per (b,f) row; lane holds output elements i=lane and i=lane+32.
// ---------------------------------------------------------------------------
__device__ __forceinline__ void ln64(float& a0, float& a1, float scale) {
    float s = a0 + a1;
    #pragma unroll
    for (int o = 16; o; o >>= 1) s += __shfl_xor_sync(0xffffffffu, s, o);
    float mu = s * (1.0f / 64.0f);
    float t0 = a0 - mu, t1 = a1 - mu;
    float ss = t0 * t0 + t1 * t1;
    #pragma unroll
    for (int o = 16; o; o >>= 1) ss += __shfl_xor_sync(0xffffffffu, ss, o);
    float r = rsqrtf(ss * (1.0f / 64.0f) + 1e-5f) * scale;
    a0 = t0 * r; a1 = t1 * r;
}

__global__ void __launch_bounds__(256) qkv_ln_kernel(
    const float* __restrict__ x,
    const float* __restrict__ Wq,
    const float* __restrict__ Wk,
    const float* __restrict__ Wv)
{
    __shared__ float sW[3 * D_ * I_];   // 28416 B
    int tid = threadIdx.x;
    for (int i = tid; i < D_ * I_; i += 256) {
        sW[i]               = Wq[i];
        sW[D_ * I_ + i]     = Wk[i];
        sW[2 * D_ * I_ + i] = Wv[i];
    }
    __syncthreads();

    int warp = tid >> 5, lane = tid & 31;
    int row = blockIdx.x * 8 + warp;            // 0 .. B*F-1
    int b = row >> 12, f = row & (F_ - 1);

    const float* xp = x + (size_t)b * D_ * F_ + f;
    float xv0 = xp[(size_t)lane * F_];                                   // d = 0..31
    float xv1 = (lane < D_ - 32) ? xp[(size_t)(lane + 32) * F_] : 0.0f;  // d = 32..36

    float q0 = 0, q1 = 0, k0 = 0, k1 = 0, v0 = 0, v1 = 0;
    #pragma unroll
    for (int d = 0; d < D_; ++d) {
        float xd = (d < 32) ? __shfl_sync(0xffffffffu, xv0, d)
                            : __shfl_sync(0xffffffffu, xv1, d - 32);
        const float* w = sW + d * I_;
        q0 += xd * w[lane];                  q1 += xd * w[lane + 32];
        k0 += xd * w[D_ * I_ + lane];        k1 += xd * w[D_ * I_ + lane + 32];
        v0 += xd * w[2 * D_ * I_ + lane];    v1 += xd * w[2 * D_ * I_ + lane + 32];
    }

    ln64(q0, q1, 0.125f);   // fold 1/sqrt(64) into q
    ln64(k0, k1, 1.0f);
    ln64(v0, v1, 1.0f);

    // qT/kT: [b][i][f]
    size_t ot = ((size_t)b * I_ + lane) * F_ + f;
    g_qT[ot] = q0;  g_qT[ot + 32 * F_] = q1;
    g_kT[ot] = k0;  g_kT[ot + 32 * F_] = k1;
    // v: [b][f][i]
    size_t ov = (size_t)row * I_ + lane;
    g_v[ov] = v0;   g_v[ov + 32] = v1;
}

// ---------------------------------------------------------------------------
// Kernel 2: S^T[b][n][m] = sum_i kT[b][i][n] * qT[b][i][m]   (q pre-scaled)
// 128x128 tile per block, K=64 in two 32-chunks, 8x8 register micro-tile.
// Both smem tiles loaded as straight float4 copies (k-major) — no transpose.
// ---------------------------------------------------------------------------
__global__ void __launch_bounds__(256) qk_gemm_kernel() {
    __shared__ float As[32][128];   // keys:    As[k][n]
    __shared__ float Bs[32][128];   // queries: Bs[k][m]

    int tid = threadIdx.x;
    int m0 = blockIdx.x * 128;      // query tile
    int n0 = blockIdx.y * 128;      // key tile
    int b  = blockIdx.z;

    const float* kT = g_kT + (size_t)b * I_ * F_;
    const float* qT = g_qT + (size_t)b * I_ * F_;

    int tx = tid & 15, ty = tid >> 4;
    float acc[8][8] = {};

    #pragma unroll
    for (int kc = 0; kc < 2; ++kc) {
        if (kc) __syncthreads();
        #pragma unroll
        for (int j = 0; j < 4; ++j) {
            int idx4 = tid + j * 256;
            int krow = idx4 >> 5;
            int c4   = (idx4 & 31) << 2;
            *(float4*)&As[krow][c4] =
                *(const float4*)&kT[(size_t)(kc * 32 + krow) * F_ + n0 + c4];
            *(float4*)&Bs[krow][c4] =
                *(const float4*)&qT[(size_t)(kc * 32 + krow) * F_ + m0 + c4];
        }
        __syncthreads();

        #pragma unroll
        for (int k = 0; k < 32; ++k) {
            float a[8], bb[8];
            *(float4*)&a[0]  = *(float4*)&As[k][ty * 8];
            *(float4*)&a[4]  = *(float4*)&As[k][ty * 8 + 4];
            *(float4*)&bb[0] = *(float4*)&Bs[k][tx * 8];
            *(float4*)&bb[4] = *(float4*)&Bs[k][tx * 8 + 4];
            #pragma unroll
            for (int r = 0; r < 8; ++r)
                #pragma unroll
                for (int c = 0; c < 8; ++c)
                    acc[r][c] += a[r] * bb[c];
        }
    }

    float* Sp = g_S + ((size_t)b << 24);
    #pragma unroll
    for (int r = 0; r < 8; ++r) {
        float* p = Sp + (size_t)(n0 + ty * 8 + r) * F_ + m0 + tx * 8;
        *(float4*)p       = *(float4*)&acc[r][0];
        *(float4*)(p + 4) = *(float4*)&acc[r][4];
    }
}

// ---------------------------------------------------------------------------
// Kernel 3: rc[b][n] = 1 / sum_m exp(S^T[b][n][m]).
// |s| <= 8 (LN rows have norm exactly 8, pre-scaled by 1/8) so no max needed.
// One warp per key row n — fully coalesced float4 streaming.
// ---------------------------------------------------------------------------
__global__ void __launch_bounds__(256) colsum_kernel() {
    int tid = threadIdx.x;
    int warp = tid >> 5, lane = tid & 31;
    int n = blockIdx.x * 8 + warp;
    int b = blockIdx.y;

    const float4* p = (const float4*)(g_S + ((size_t)b << 24) + (size_t)n * F_);
    float s = 0.0f;
    #pragma unroll 4
    for (int j = 0; j < F_ / 128; ++j) {   // 32 iters of float4 per lane
        float4 v = p[lane + j * 32];
        s += __expf(v.x) + __expf(v.y) + __expf(v.z) + __expf(v.w);
    }
    #pragma unroll
    for (int o = 16; o; o >>= 1) s += __shfl_xor_sync(0xffffffffu, s, o);
    if (lane == 0) g_rc[b * F_ + n] = 1.0f / s;
}

// ---------------------------------------------------------------------------
// Kernel 4: out[b][m][i] = sum_n exp(S^T[b][n][m]) * v[b][n][i] * rc[b][n]
// 128(m) x 64(i) tile per block, n in 32-chunks. exp fused into the smem load;
// rc fused into the V load. 8x4 register micro-tile. No smem transposes.
// ---------------------------------------------------------------------------
__global__ void __launch_bounds__(256) av_gemm_kernel(float* __restrict__ out) {
    __shared__ float Ps[32][128];   // Ps[nn][m] = exp(S^T[n][m])
    __shared__ float Vs[32][64];    // Vs[nn][i] = v[n][i] * rc[n]

    int tid = threadIdx.x;
    int m0 = blockIdx.x * 128;
    int b  = blockIdx.y;

    const float* Sp  = g_S  + ((size_t)b << 24);
    const float* vp  = g_v  + (size_t)b * F_ * I_;
    const float* rcp = g_rc + b * F_;

    int tx = tid & 15, ty = tid >> 4;
    float acc[8][4] = {};

    for (int nt = 0; nt < F_; nt += 32) {
        #pragma unroll
        for (int j = 0; j < 4; ++j) {
            int idx4 = tid + j * 256;
            int nn = idx4 >> 5;
            int m4 = (idx4 & 31) << 2;
            float4 s4 = *(const float4*)&Sp[(size_t)(nt + nn) * F_ + m0 + m4];
            s4.x = __expf(s4.x); s4.y = __expf(s4.y);
            s4.z = __expf(s4.z); s4.w = __expf(s4.w);
            *(float4*)&Ps[nn][m4] = s4;
        }
        #pragma unroll
        for (int j = 0; j < 2; ++j) {
            int idx4 = tid + j * 256;
            int nn = idx4 >> 4;
            int i4 = (idx4 & 15) << 2;
            float rc = rcp[nt + nn];
            float4 v4 = *(const float4*)&vp[(size_t)(nt + nn) * I_ + i4];
            v4.x *= rc; v4.y *= rc; v4.z *= rc; v4.w *= rc;
            *(float4*)&Vs[nn][i4] = v4;
        }
        __syncthreads();

        #pragma unroll
        for (int nn = 0; nn < 32; ++nn) {
            float a[8], bv[4];
            *(float4*)&a[0]  = *(float4*)&Ps[nn][ty * 8];
            *(float4*)&a[4]  = *(float4*)&Ps[nn][ty * 8 + 4];
            *(float4*)&bv[0] = *(float4*)&Vs[nn][tx * 4];
            #pragma unroll
            for (int r = 0; r < 8; ++r)
                #pragma unroll
                for (int c = 0; c < 4; ++c)
                    acc[r][c] += a[r] * bv[c];
        }
        __syncthreads();
    }

    #pragma unroll
    for (int r = 0; r < 8; ++r)
        *(float4*)&out[((size_t)b * F_ + m0 + ty * 8 + r) * I_ + tx * 4] =
            *(float4*)&acc[r][0];
}

// ---------------------------------------------------------------------------
extern "C" void kernel_launch(void* const* d_in, const int* in_sizes, int n_in,
                              void* d_out, int out_size)
{
    const float* x  = (const float*)d_in[0];
    const float* Wq = (const float*)d_in[1];
    const float* Wk = (const float*)d_in[2];
    const float* Wv = (const float*)d_in[3];
    float* out = (float*)d_out;

    qkv_ln_kernel<<<B_ * F_ / 8, 256>>>(x, Wq, Wk, Wv);
    qk_gemm_kernel<<<dim3(F_ / 128, F_ / 128, B_), 256>>>();
    colsum_kernel<<<dim3(F_ / 8, B_), 256>>>();
    av_gemm_kernel<<<dim3(F_ / 128, B_), 256>>>(out);
}

// round 3
// speedup vs baseline: 1.2284x; 1.2284x over previous
#include <cuda_runtime.h>
#include <cuda_bf16.h>
#include <cstdint>
#include <math.h>

#define B_ 16
#define D_ 37
#define F_ 4096
#define I_ 64

// ---- scratch (static device globals: allocation-free) ----
__device__ float g_qT[B_ * I_ * F_];                 // [b][i][f], LN'd, pre-scaled by 1/8
__device__ float g_kT[B_ * I_ * F_];                 // [b][i][f], LN'd
__device__ float g_v [B_ * F_ * I_];                 // [b][f][i], LN'd
__device__ float g_c [B_ * F_];                      // column sums: c[n] = sum_m exp(S^T[n][m])
__device__ __nv_bfloat16 g_P[(size_t)B_ * F_ * F_];  // P^T = exp(S^T) [b][key n][query m], bf16

// ---------------------------------------------------------------------------
// Kernel 0: zero the column-sum accumulator (graph-replay safe).
// ---------------------------------------------------------------------------
__global__ void zero_c_kernel() {
    g_c[blockIdx.x * 256 + threadIdx.x] = 0.0f;
}

// ---------------------------------------------------------------------------
// Kernel 1: q/k/v = LN(x^T @ W); q pre-scaled by 1/sqrt(64); q,k stored
// transposed [b][i][f]. One warp per (b,f) row.
// ---------------------------------------------------------------------------
__device__ __forceinline__ void ln64(float& a0, float& a1, float scale) {
    float s = a0 + a1;
    #pragma unroll
    for (int o = 16; o; o >>= 1) s += __shfl_xor_sync(0xffffffffu, s, o);
    float mu = s * (1.0f / 64.0f);
    float t0 = a0 - mu, t1 = a1 - mu;
    float ss = t0 * t0 + t1 * t1;
    #pragma unroll
    for (int o = 16; o; o >>= 1) ss += __shfl_xor_sync(0xffffffffu, ss, o);
    float r = rsqrtf(ss * (1.0f / 64.0f) + 1e-5f) * scale;
    a0 = t0 * r; a1 = t1 * r;
}

__global__ void __launch_bounds__(256) qkv_ln_kernel(
    const float* __restrict__ x,
    const float* __restrict__ Wq,
    const float* __restrict__ Wk,
    const float* __restrict__ Wv)
{
    __shared__ float sW[3 * D_ * I_];
    int tid = threadIdx.x;
    for (int i = tid; i < D_ * I_; i += 256) {
        sW[i]               = Wq[i];
        sW[D_ * I_ + i]     = Wk[i];
        sW[2 * D_ * I_ + i] = Wv[i];
    }
    __syncthreads();

    int warp = tid >> 5, lane = tid & 31;
    int row = blockIdx.x * 8 + warp;
    int b = row >> 12, f = row & (F_ - 1);

    const float* xp = x + (size_t)b * D_ * F_ + f;
    float xv0 = xp[(size_t)lane * F_];
    float xv1 = (lane < D_ - 32) ? xp[(size_t)(lane + 32) * F_] : 0.0f;

    float q0 = 0, q1 = 0, k0 = 0, k1 = 0, v0 = 0, v1 = 0;
    #pragma unroll
    for (int d = 0; d < D_; ++d) {
        float xd = (d < 32) ? __shfl_sync(0xffffffffu, xv0, d)
                            : __shfl_sync(0xffffffffu, xv1, d - 32);
        const float* w = sW + d * I_;
        q0 += xd * w[lane];                  q1 += xd * w[lane + 32];
        k0 += xd * w[D_ * I_ + lane];        k1 += xd * w[D_ * I_ + lane + 32];
        v0 += xd * w[2 * D_ * I_ + lane];    v1 += xd * w[2 * D_ * I_ + lane + 32];
    }

    ln64(q0, q1, 0.125f);
    ln64(k0, k1, 1.0f);
    ln64(v0, v1, 1.0f);

    size_t ot = ((size_t)b * I_ + lane) * F_ + f;
    g_qT[ot] = q0;  g_qT[ot + 32 * F_] = q1;
    g_kT[ot] = k0;  g_kT[ot + 32 * F_] = k1;
    size_t ov = (size_t)row * I_ + lane;
    g_v[ov] = v0;   g_v[ov + 32] = v1;
}

// ---------------------------------------------------------------------------
// Kernel 2: S^T[n][m] = sum_i kT[i][n]*qT[i][m]; epilogue computes
// P = exp(S^T) (bf16, stored), and row-sums of P (= softmax column sums)
// accumulated into g_c via atomics. Full K=64 panel in smem (64 KB dynamic).
// ---------------------------------------------------------------------------
__global__ void __launch_bounds__(256) qk_gemm_kernel() {
    extern __shared__ float smqk[];
    float* As = smqk;             // [64][128] keys
    float* Bs = smqk + 64 * 128;  // [64][128] queries

    int tid = threadIdx.x;
    int m0 = blockIdx.x * 128;    // query tile
    int n0 = blockIdx.y * 128;    // key tile
    int b  = blockIdx.z;

    const float* kT = g_kT + (size_t)b * I_ * F_;
    const float* qT = g_qT + (size_t)b * I_ * F_;

    #pragma unroll
    for (int j = 0; j < 8; ++j) {
        int idx4 = tid + j * 256;       // 2048 float4 loads per tile
        int krow = idx4 >> 5;
        int c4   = (idx4 & 31) << 2;
        *(float4*)&As[krow * 128 + c4] = *(const float4*)&kT[(size_t)krow * F_ + n0 + c4];
        *(float4*)&Bs[krow * 128 + c4] = *(const float4*)&qT[(size_t)krow * F_ + m0 + c4];
    }
    __syncthreads();

    int tx = tid & 15, ty = tid >> 4;   // tx -> m, ty -> n
    float acc[8][8] = {};

    #pragma unroll 8
    for (int k = 0; k < 64; ++k) {
        float a[8], bb[8];
        *(float4*)&a[0]  = *(float4*)&As[k * 128 + ty * 8];
        *(float4*)&a[4]  = *(float4*)&As[k * 128 + ty * 8 + 4];
        *(float4*)&bb[0] = *(float4*)&Bs[k * 128 + tx * 8];
        *(float4*)&bb[4] = *(float4*)&Bs[k * 128 + tx * 8 + 4];
        #pragma unroll
        for (int r = 0; r < 8; ++r)
            #pragma unroll
            for (int c = 0; c < 8; ++c)
                acc[r][c] += a[r] * bb[c];
    }

    // Epilogue: exp, pack bf16, write P, accumulate row sums into g_c.
    __nv_bfloat16* Pp = g_P + ((size_t)b << 24);
    float rs[8];
    #pragma unroll
    for (int r = 0; r < 8; ++r) {
        __nv_bfloat162 h[4];
        rs[r] = 0.0f;
        #pragma unroll
        for (int c2 = 0; c2 < 4; ++c2) {
            float e0 = __expf(acc[r][2 * c2]);
            float e1 = __expf(acc[r][2 * c2 + 1]);
            rs[r] += e0 + e1;
            h[c2] = __floats2bfloat162_rn(e0, e1);
        }
        *(uint4*)(Pp + (size_t)(n0 + ty * 8 + r) * F_ + m0 + tx * 8) = *(uint4*)h;
    }
    #pragma unroll
    for (int o = 1; o < 16; o <<= 1)
        #pragma unroll
        for (int r = 0; r < 8; ++r)
            rs[r] += __shfl_xor_sync(0xffffffffu, rs[r], o);
    if (tx == 0) {
        #pragma unroll
        for (int r = 0; r < 8; ++r)
            atomicAdd(&g_c[b * F_ + n0 + ty * 8 + r], rs[r]);
    }
}

// ---------------------------------------------------------------------------
// Kernel 4: out[m][i] = sum_n P[n][m] * v[n][i] / c[n].
// 256(m) x 64(i) tile, 8x8 micro-tile, double-buffered smem with register
// prefetch, one __syncthreads per chunk. P read as bf16, converted on the
// smem-store path; 1/c folded into the V smem tile.
// ---------------------------------------------------------------------------
#define PS(buf, nn, m) smav[(buf) * 8192 + (nn) * 256 + (m)]
#define VS(buf, nn, i) smav[16384 + (buf) * 2048 + (nn) * 64 + (i)]

__global__ void __launch_bounds__(256, 2) av_gemm_kernel(float* __restrict__ out) {
    extern __shared__ float smav[];   // Ps[2][32][256] + Vs[2][32][64] = 80 KB

    int tid = threadIdx.x;
    int m0 = blockIdx.x * 256;
    int b  = blockIdx.y;

    const __nv_bfloat16* Pp = g_P + ((size_t)b << 24);
    const float* vp  = g_v + (size_t)b * F_ * I_;
    const float* cp  = g_c + b * F_;

    int tx = tid & 7, ty = tid >> 3;  // tx -> i (8x8=64), ty -> m (32x8=256)
    float acc[8][8] = {};
    uint4 pr[4];
    float4 vr[2];

    // ---- prologue: chunk 0 ----
    #pragma unroll
    for (int j = 0; j < 4; ++j) {
        int idx = tid + j * 256;
        int nn = idx >> 5, c8 = (idx & 31) << 3;
        pr[j] = *(const uint4*)(Pp + (size_t)nn * F_ + m0 + c8);
    }
    #pragma unroll
    for (int j = 0; j < 2; ++j) {
        int idx = tid + j * 256;
        int nn = idx >> 4, i4 = (idx & 15) << 2;
        vr[j] = *(const float4*)&vp[(size_t)nn * I_ + i4];
        float rc = 1.0f / cp[nn];
        vr[j].x *= rc; vr[j].y *= rc; vr[j].z *= rc; vr[j].w *= rc;
    }
    #pragma unroll
    for (int j = 0; j < 4; ++j) {
        int idx = tid + j * 256;
        int nn = idx >> 5, c8 = (idx & 31) << 3;
        unsigned int us[4] = {pr[j].x, pr[j].y, pr[j].z, pr[j].w};
        float f[8];
        #pragma unroll
        for (int t2 = 0; t2 < 4; ++t2) {
            f[2 * t2]     = __uint_as_float(us[t2] << 16);
            f[2 * t2 + 1] = __uint_as_float(us[t2] & 0xffff0000u);
        }
        *(float4*)&PS(0, nn, c8)     = *(float4*)&f[0];
        *(float4*)&PS(0, nn, c8 + 4) = *(float4*)&f[4];
    }
    #pragma unroll
    for (int j = 0; j < 2; ++j) {
        int idx = tid + j * 256;
        int nn = idx >> 4, i4 = (idx & 15) << 2;
        *(float4*)&VS(0, nn, i4) = vr[j];
    }
    __syncthreads();

    // ---- main loop over 128 chunks of 32 keys ----
    for (int t = 0; t < F_ / 32; ++t) {
        int buf = t & 1;
        bool has_next = (t + 1) < F_ / 32;
        int nt1 = (t + 1) * 32;

        if (has_next) {
            #pragma unroll
            for (int j = 0; j < 4; ++j) {
                int idx = tid + j * 256;
                int nn = idx >> 5, c8 = (idx & 31) << 3;
                pr[j] = *(const uint4*)(Pp + (size_t)(nt1 + nn) * F_ + m0 + c8);
            }
            #pragma unroll
            for (int j = 0; j < 2; ++j) {
                int idx = tid + j * 256;
                int nn = idx >> 4, i4 = (idx & 15) << 2;
                vr[j] = *(const float4*)&vp[(size_t)(nt1 + nn) * I_ + i4];
                float rc = 1.0f / cp[nt1 + nn];
                vr[j].x *= rc; vr[j].y *= rc; vr[j].z *= rc; vr[j].w *= rc;
            }
        }

        #pragma unroll 8
        for (int nn = 0; nn < 32; ++nn) {
            float a[8], bv[8];
            *(float4*)&a[0]  = *(float4*)&PS(buf, nn, ty * 8);
            *(float4*)&a[4]  = *(float4*)&PS(buf, nn, ty * 8 + 4);
            *(float4*)&bv[0] = *(float4*)&VS(buf, nn, tx * 8);
            *(float4*)&bv[4] = *(float4*)&VS(buf, nn, tx * 8 + 4);
            #pragma unroll
            for (int r = 0; r < 8; ++r)
                #pragma unroll
                for (int c = 0; c < 8; ++c)
                    acc[r][c] += a[r] * bv[c];
        }

        if (has_next) {
            int nb = buf ^ 1;
            #pragma unroll
            for (int j = 0; j < 4; ++j) {
                int idx = tid + j * 256;
                int nn = idx >> 5, c8 = (idx & 31) << 3;
                unsigned int us[4] = {pr[j].x, pr[j].y, pr[j].z, pr[j].w};
                float f[8];
                #pragma unroll
                for (int t2 = 0; t2 < 4; ++t2) {
                    f[2 * t2]     = __uint_as_float(us[t2] << 16);
                    f[2 * t2 + 1] = __uint_as_float(us[t2] & 0xffff0000u);
                }
                *(float4*)&PS(nb, nn, c8)     = *(float4*)&f[0];
                *(float4*)&PS(nb, nn, c8 + 4) = *(float4*)&f[4];
            }
            #pragma unroll
            for (int j = 0; j < 2; ++j) {
                int idx = tid + j * 256;
                int nn = idx >> 4, i4 = (idx & 15) << 2;
                *(float4*)&VS(nb, nn, i4) = vr[j];
            }
        }
        __syncthreads();
    }

    #pragma unroll
    for (int r = 0; r < 8; ++r) {
        float* p = &out[((size_t)b * F_ + m0 + ty * 8 + r) * I_ + tx * 8];
        *(float4*)p       = *(float4*)&acc[r][0];
        *(float4*)(p + 4) = *(float4*)&acc[r][4];
    }
}

// ---------------------------------------------------------------------------
extern "C" void kernel_launch(void* const* d_in, const int* in_sizes, int n_in,
                              void* d_out, int out_size)
{
    const float* x  = (const float*)d_in[0];
    const float* Wq = (const float*)d_in[1];
    const float* Wk = (const float*)d_in[2];
    const float* Wv = (const float*)d_in[3];
    float* out = (float*)d_out;

    static bool attr_done = false;
    if (!attr_done) {
        cudaFuncSetAttribute(qk_gemm_kernel,
                             cudaFuncAttributeMaxDynamicSharedMemorySize, 65536);
        cudaFuncSetAttribute(av_gemm_kernel,
                             cudaFuncAttributeMaxDynamicSharedMemorySize, 81920);
        attr_done = true;
    }

    zero_c_kernel<<<B_ * F_ / 256, 256>>>();
    qkv_ln_kernel<<<B_ * F_ / 8, 256>>>(x, Wq, Wk, Wv);
    qk_gemm_kernel<<<dim3(F_ / 128, F_ / 128, B_), 256, 65536>>>();
    av_gemm_kernel<<<dim3(F_ / 256, B_), 256, 81920>>>(out);
}

// round 5
// speedup vs baseline: 2.1082x; 1.7162x over previous
#include <cuda_runtime.h>
#include <cuda_bf16.h>
#include <cstdint>
#include <math.h>

#define B_ 16
#define D_ 37
#define F_ 4096
#define I_ 64

// ---- scratch (static device globals: allocation-free) ----
__device__ float g_qT[B_ * I_ * F_];                 // [b][i][f], LN'd, pre-scaled by 1/8
__device__ float g_kT[B_ * I_ * F_];                 // [b][i][f], LN'd
__device__ float g_v [B_ * F_ * I_];                 // [b][f][i], LN'd fp32
__device__ float g_c [B_ * F_];                      // c[n] = sum_m exp(S[m][n])
__device__ __nv_bfloat16 g_P [(size_t)B_ * F_ * F_]; // P[b][m][n] = exp(S), bf16, n contig
__device__ __nv_bfloat16 g_vs[B_ * F_ * I_];         // Vs[b][n][i] = v[n][i]/c[n], bf16

#define SW128B(o) ((o) ^ (((o) >> 3) & 0x70))

// ======================= PTX helpers (arch-generic, sm_80+) ==================
__device__ __forceinline__ unsigned smem_u32(const void* p) {
    unsigned a;
    asm("{ .reg .u64 t; cvta.to.shared.u64 t, %1; cvt.u32.u64 %0, t; }"
        : "=r"(a) : "l"(p));
    return a;
}
__device__ __forceinline__ void cp_async16(unsigned dst, const void* src) {
    asm volatile("cp.async.cg.shared.global [%0], [%1], 16;" :: "r"(dst), "l"(src));
}
__device__ __forceinline__ void cp_commit() {
    asm volatile("cp.async.commit_group;" ::: "memory");
}
template <int N>
__device__ __forceinline__ void cp_wait() {
    asm volatile("cp.async.wait_group %0;" :: "n"(N) : "memory");
}
__device__ __forceinline__ void ldm_x4(unsigned* r, unsigned addr) {
    asm volatile("ldmatrix.sync.aligned.m8n8.x4.shared.b16 {%0,%1,%2,%3}, [%4];"
                 : "=r"(r[0]), "=r"(r[1]), "=r"(r[2]), "=r"(r[3]) : "r"(addr));
}
__device__ __forceinline__ void ldm_x4_t(unsigned* r, unsigned addr) {
    asm volatile("ldmatrix.sync.aligned.m8n8.x4.trans.shared.b16 {%0,%1,%2,%3}, [%4];"
                 : "=r"(r[0]), "=r"(r[1]), "=r"(r[2]), "=r"(r[3]) : "r"(addr));
}
__device__ __forceinline__ void mma_bf16(float* c, const unsigned* a,
                                         unsigned b0, unsigned b1) {
    asm volatile(
        "mma.sync.aligned.m16n8k16.row.col.f32.bf16.bf16.f32 "
        "{%0,%1,%2,%3}, {%4,%5,%6,%7}, {%8,%9}, {%0,%1,%2,%3};"
        : "+f"(c[0]), "+f"(c[1]), "+f"(c[2]), "+f"(c[3])
        : "r"(a[0]), "r"(a[1]), "r"(a[2]), "r"(a[3]), "r"(b0), "r"(b1));
}

// ---------------------------------------------------------------------------
// Kernel 0: zero the column-sum accumulator (graph-replay safe).
// ---------------------------------------------------------------------------
__global__ void zero_c_kernel() {
    g_c[blockIdx.x * 256 + threadIdx.x] = 0.0f;
}

// ---------------------------------------------------------------------------
// Kernel 1: q/k/v = LN(x^T @ W); q pre-scaled by 1/sqrt(64); q,k stored
// transposed [b][i][f]; v stored [b][f][i]. One warp per (b,f) row.
// ---------------------------------------------------------------------------
__device__ __forceinline__ void ln64(float& a0, float& a1, float scale) {
    float s = a0 + a1;
    #pragma unroll
    for (int o = 16; o; o >>= 1) s += __shfl_xor_sync(0xffffffffu, s, o);
    float mu = s * (1.0f / 64.0f);
    float t0 = a0 - mu, t1 = a1 - mu;
    float ss = t0 * t0 + t1 * t1;
    #pragma unroll
    for (int o = 16; o; o >>= 1) ss += __shfl_xor_sync(0xffffffffu, ss, o);
    float r = rsqrtf(ss * (1.0f / 64.0f) + 1e-5f) * scale;
    a0 = t0 * r; a1 = t1 * r;
}

__global__ void __launch_bounds__(256) qkv_ln_kernel(
    const float* __restrict__ x,
    const float* __restrict__ Wq,
    const float* __restrict__ Wk,
    const float* __restrict__ Wv)
{
    __shared__ float sW[3 * D_ * I_];
    int tid = threadIdx.x;
    for (int i = tid; i < D_ * I_; i += 256) {
        sW[i]               = Wq[i];
        sW[D_ * I_ + i]     = Wk[i];
        sW[2 * D_ * I_ + i] = Wv[i];
    }
    __syncthreads();

    int warp = tid >> 5, lane = tid & 31;
    int row = blockIdx.x * 8 + warp;
    int b = row >> 12, f = row & (F_ - 1);

    const float* xp = x + (size_t)b * D_ * F_ + f;
    float xv0 = xp[(size_t)lane * F_];
    float xv1 = (lane < D_ - 32) ? xp[(size_t)(lane + 32) * F_] : 0.0f;

    float q0 = 0, q1 = 0, k0 = 0, k1 = 0, v0 = 0, v1 = 0;
    #pragma unroll
    for (int d = 0; d < D_; ++d) {
        float xd = (d < 32) ? __shfl_sync(0xffffffffu, xv0, d)
                            : __shfl_sync(0xffffffffu, xv1, d - 32);
        const float* w = sW + d * I_;
        q0 += xd * w[lane];                  q1 += xd * w[lane + 32];
        k0 += xd * w[D_ * I_ + lane];        k1 += xd * w[D_ * I_ + lane + 32];
        v0 += xd * w[2 * D_ * I_ + lane];    v1 += xd * w[2 * D_ * I_ + lane + 32];
    }

    ln64(q0, q1, 0.125f);
    ln64(k0, k1, 1.0f);
    ln64(v0, v1, 1.0f);

    size_t ot = ((size_t)b * I_ + lane) * F_ + f;
    g_qT[ot] = q0;  g_qT[ot + 32 * F_] = q1;
    g_kT[ot] = k0;  g_kT[ot + 32 * F_] = k1;
    size_t ov = (size_t)row * I_ + lane;
    g_v[ov] = v0;   g_v[ov + 32] = v1;
}

// ---------------------------------------------------------------------------
// Kernel 2: S[m][n] = sum_i qT[i][m]*kT[i][n]; epilogue stores P=exp(S) as
// bf16 in [b][m][n] layout and accumulates column sums c[n] via smem staging
// + one global atomic per n per block.
// ---------------------------------------------------------------------------
__global__ void __launch_bounds__(256) qk_gemm_kernel() {
    extern __shared__ float smqk[];
    float* As   = smqk;                 // [64][128] queries (m)
    float* Bs   = smqk + 64 * 128;      // [64][128] keys    (n)
    float* scol = smqk + 2 * 64 * 128;  // [128] column sums

    int tid = threadIdx.x;
    int m0 = blockIdx.x * 128;
    int n0 = blockIdx.y * 128;
    int b  = blockIdx.z;

    const float* qT = g_qT + (size_t)b * I_ * F_;
    const float* kT = g_kT + (size_t)b * I_ * F_;

    if (tid < 128) scol[tid] = 0.0f;
    #pragma unroll
    for (int j = 0; j < 8; ++j) {
        int idx4 = tid + j * 256;
        int krow = idx4 >> 5;
        int c4   = (idx4 & 31) << 2;
        *(float4*)&As[krow * 128 + c4] = *(const float4*)&qT[(size_t)krow * F_ + m0 + c4];
        *(float4*)&Bs[krow * 128 + c4] = *(const float4*)&kT[(size_t)krow * F_ + n0 + c4];
    }
    __syncthreads();

    int tx = tid & 15, ty = tid >> 4;   // ty -> m, tx -> n
    float acc[8][8] = {};

    #pragma unroll 8
    for (int k = 0; k < 64; ++k) {
        float a[8], bb[8];
        *(float4*)&a[0]  = *(float4*)&As[k * 128 + ty * 8];
        *(float4*)&a[4]  = *(float4*)&As[k * 128 + ty * 8 + 4];
        *(float4*)&bb[0] = *(float4*)&Bs[k * 128 + tx * 8];
        *(float4*)&bb[4] = *(float4*)&Bs[k * 128 + tx * 8 + 4];
        #pragma unroll
        for (int r = 0; r < 8; ++r)
            #pragma unroll
            for (int c = 0; c < 8; ++c)
                acc[r][c] += a[r] * bb[c];
    }

    __nv_bfloat16* Pp = g_P + ((size_t)b << 24);
    float colp[8] = {};
    #pragma unroll
    for (int r = 0; r < 8; ++r) {
        __nv_bfloat162 h[4];
        #pragma unroll
        for (int c2 = 0; c2 < 4; ++c2) {
            float e0 = __expf(acc[r][2 * c2]);
            float e1 = __expf(acc[r][2 * c2 + 1]);
            colp[2 * c2]     += e0;
            colp[2 * c2 + 1] += e1;
            h[c2] = __floats2bfloat162_rn(e0, e1);
        }
        *(uint4*)(Pp + (size_t)(m0 + ty * 8 + r) * F_ + n0 + tx * 8) = *(uint4*)h;
    }
    #pragma unroll
    for (int c = 0; c < 8; ++c)
        colp[c] += __shfl_xor_sync(0xffffffffu, colp[c], 16);
    if ((ty & 1) == 0) {
        #pragma unroll
        for (int c = 0; c < 8; ++c)
            atomicAdd(&scol[tx * 8 + c], colp[c]);
    }
    __syncthreads();
    if (tid < 128) atomicAdd(&g_c[b * F_ + n0 + tid], scol[tid]);
}

// ---------------------------------------------------------------------------
// Kernel 3: g_vs[b][n][i] = bf16( v[b][n][i] / c[b][n] ). 8 elems/thread.
// ---------------------------------------------------------------------------
__global__ void __launch_bounds__(256) vscale_kernel() {
    size_t e = ((size_t)blockIdx.x * 256 + threadIdx.x) * 8;
    int row = (int)(e >> 6);             // b*F + n
    float rc = 1.0f / g_c[row];

    const float* vp = g_v + e;
    float4 v0 = *(const float4*)vp;
    float4 v1 = *(const float4*)(vp + 4);

    __nv_bfloat162 h[4];
    h[0] = __floats2bfloat162_rn(v0.x * rc, v0.y * rc);
    h[1] = __floats2bfloat162_rn(v0.z * rc, v0.w * rc);
    h[2] = __floats2bfloat162_rn(v1.x * rc, v1.y * rc);
    h[3] = __floats2bfloat162_rn(v1.z * rc, v1.w * rc);
    *(uint4*)(g_vs + e) = *(uint4*)h;
}

// ---------------------------------------------------------------------------
// Kernel 4: out[m][i] = sum_n P[m][n] * Vs[n][i]  via HMMA mma.sync bf16.
// Block: 256 thr, tile 256(m) x 64(i), K=4096 in 64 chunks of 64.
// cp.async double-buffered smem (SW128-swizzled 128B rows), ldmatrix operands.
// ---------------------------------------------------------------------------
#define AV_P0   0u
#define AV_PSZ  32768u
#define AV_V0   65536u
#define AV_VSZ  8192u
#define AV_SMEM 81920

__global__ void __launch_bounds__(256) av_hmma_kernel(float* __restrict__ out) {
    extern __shared__ char sm[];
    unsigned sb = smem_u32(sm);

    int tid = threadIdx.x, lane = tid & 31, w = tid >> 5;
    int m0 = blockIdx.x * 256;
    int b  = blockIdx.y;

    const __nv_bfloat16* Pb = g_P  + ((size_t)b << 24);
    const __nv_bfloat16* Vb = g_vs + (size_t)b * F_ * I_;

    // per-thread load indices
    int pr  = tid >> 3;            // P row (0..255 over j), base row tid>>3
    int pc  = (tid & 7) << 4;      // byte col within 128B row

    float acc[2][8][4] = {};

    // ---- fill chunk 0 ----
    {
        #pragma unroll
        for (int j = 0; j < 8; ++j) {
            int r = pr + j * 32;
            cp_async16(sb + AV_P0 + SW128B((unsigned)(r * 128 + pc)),
                       Pb + (size_t)(m0 + r) * F_ + (pc >> 1));
        }
        #pragma unroll
        for (int j = 0; j < 2; ++j) {
            int r = pr + j * 32;
            cp_async16(sb + AV_V0 + SW128B((unsigned)(r * 128 + pc)),
                       Vb + (size_t)r * I_ + (pc >> 1));
        }
        cp_commit();
    }

    // ldmatrix base offsets (within a buffer)
    unsigned a_row = (unsigned)((w * 32 + (lane & 15)) * 128 + ((lane >> 4) << 4));
    unsigned b_row = (unsigned)(((lane & 15)) * 128 + ((lane >> 4) << 4));

    for (int t = 0; t < F_ / 64; ++t) {
        unsigned pbuf = sb + AV_P0 + (t & 1) * AV_PSZ;
        unsigned vbuf = sb + AV_V0 + (t & 1) * AV_VSZ;

        if (t < F_ / 64 - 1) {
            int kc = (t + 1) * 64;
            unsigned pd = sb + AV_P0 + ((t + 1) & 1) * AV_PSZ;
            unsigned vd = sb + AV_V0 + ((t + 1) & 1) * AV_VSZ;
            #pragma unroll
            for (int j = 0; j < 8; ++j) {
                int r = pr + j * 32;
                cp_async16(pd + SW128B((unsigned)(r * 128 + pc)),
                           Pb + (size_t)(m0 + r) * F_ + kc + (pc >> 1));
            }
            #pragma unroll
            for (int j = 0; j < 2; ++j) {
                int r = pr + j * 32;
                cp_async16(vd + SW128B((unsigned)(r * 128 + pc)),
                           Vb + (size_t)(kc + r) * I_ + (pc >> 1));
            }
            cp_commit();
            cp_wait<1>();
        } else {
            cp_wait<0>();
        }
        __syncthreads();

        #pragma unroll
        for (int s = 0; s < 4; ++s) {
            unsigned a[2][4], bv[4][4];
            ldm_x4(a[0], pbuf + SW128B(a_row + s * 32));
            ldm_x4(a[1], pbuf + SW128B(a_row + 2048 + s * 32));   // +16 rows
            #pragma unroll
            for (int p = 0; p < 4; ++p)
                ldm_x4_t(bv[p], vbuf + SW128B(b_row + s * 2048 + p * 32));

            #pragma unroll
            for (int mt = 0; mt < 2; ++mt)
                #pragma unroll
                for (int p = 0; p < 4; ++p) {
                    mma_bf16(acc[mt][2 * p],     a[mt], bv[p][0], bv[p][1]);
                    mma_bf16(acc[mt][2 * p + 1], a[mt], bv[p][2], bv[p][3]);
                }
        }
        __syncthreads();
    }

    // epilogue: D fragment rows = lane>>2 (+8), cols = (lane&3)*2
    int mrow = m0 + w * 32 + (lane >> 2);
    int col  = (lane & 3) * 2;
    #pragma unroll
    for (int mt = 0; mt < 2; ++mt) {
        float* o0 = out + ((size_t)b * F_ + mrow + mt * 16) * I_ + col;
        float* o1 = o0 + 8 * I_;
        #pragma unroll
        for (int it = 0; it < 8; ++it) {
            *(float2*)(o0 + it * 8) = make_float2(acc[mt][it][0], acc[mt][it][1]);
            *(float2*)(o1 + it * 8) = make_float2(acc[mt][it][2], acc[mt][it][3]);
        }
    }
}

// ---------------------------------------------------------------------------
extern "C" void kernel_launch(void* const* d_in, const int* in_sizes, int n_in,
                              void* d_out, int out_size)
{
    const float* x  = (const float*)d_in[0];
    const float* Wq = (const float*)d_in[1];
    const float* Wk = (const float*)d_in[2];
    const float* Wv = (const float*)d_in[3];
    float* out = (float*)d_out;

    static bool attr_done = false;
    if (!attr_done) {
        cudaFuncSetAttribute(qk_gemm_kernel,
                             cudaFuncAttributeMaxDynamicSharedMemorySize,
                             2 * 64 * 128 * 4 + 128 * 4);
        cudaFuncSetAttribute(av_hmma_kernel,
                             cudaFuncAttributeMaxDynamicSharedMemorySize, AV_SMEM);
        attr_done = true;
    }

    zero_c_kernel<<<B_ * F_ / 256, 256>>>();
    qkv_ln_kernel<<<B_ * F_ / 8, 256>>>(x, Wq, Wk, Wv);
    qk_gemm_kernel<<<dim3(F_ / 128, F_ / 128, B_), 256, 2 * 64 * 128 * 4 + 128 * 4>>>();
    vscale_kernel<<<B_ * F_ * I_ / (256 * 8), 256>>>();
    av_hmma_kernel<<<dim3(F_ / 256, B_), 256, AV_SMEM>>>(out);
}

// round 6
// speedup vs baseline: 3.6174x; 1.7159x over previous
#include <cuda_runtime.h>
#include <cuda_bf16.h>
#include <cstdint>
#include <math.h>

#define B_ 16
#define D_ 37
#define F_ 4096
#define I_ 64

// ---- scratch (static device globals: allocation-free) ----
__device__ float g_q [B_ * F_ * I_];                 // [b][f][i], LN'd, /8, tf32-rounded
__device__ float g_k [B_ * F_ * I_];                 // [b][f][i], LN'd, tf32-rounded
__device__ float g_v [B_ * F_ * I_];                 // [b][f][i], LN'd fp32
__device__ float g_c [B_ * F_];                      // c[n] = sum_m exp(S[m][n])
__device__ __nv_bfloat16 g_P [(size_t)B_ * F_ * F_]; // P[b][m][n] = exp(S), bf16, n contig
__device__ __nv_bfloat16 g_vs[B_ * F_ * I_];         // Vs[b][n][i] = v[n][i]/c[n], bf16

#define SW128B(o) ((o) ^ (((o) >> 3) & 0x70))
#define SW256B(o) ((o) ^ (((o) >> 4) & 0x70))

// ======================= PTX helpers (arch-generic, sm_80+) ==================
__device__ __forceinline__ unsigned smem_u32(const void* p) {
    unsigned a;
    asm("{ .reg .u64 t; cvta.to.shared.u64 t, %1; cvt.u32.u64 %0, t; }"
        : "=r"(a) : "l"(p));
    return a;
}
__device__ __forceinline__ void cp_async16(unsigned dst, const void* src) {
    asm volatile("cp.async.cg.shared.global [%0], [%1], 16;" :: "r"(dst), "l"(src));
}
__device__ __forceinline__ void cp_commit() {
    asm volatile("cp.async.commit_group;" ::: "memory");
}
template <int N>
__device__ __forceinline__ void cp_wait() {
    asm volatile("cp.async.wait_group %0;" :: "n"(N) : "memory");
}
__device__ __forceinline__ void ldm_x4(unsigned* r, unsigned addr) {
    asm volatile("ldmatrix.sync.aligned.m8n8.x4.shared.b16 {%0,%1,%2,%3}, [%4];"
                 : "=r"(r[0]), "=r"(r[1]), "=r"(r[2]), "=r"(r[3]) : "r"(addr));
}
__device__ __forceinline__ void ldm_x4_t(unsigned* r, unsigned addr) {
    asm volatile("ldmatrix.sync.aligned.m8n8.x4.trans.shared.b16 {%0,%1,%2,%3}, [%4];"
                 : "=r"(r[0]), "=r"(r[1]), "=r"(r[2]), "=r"(r[3]) : "r"(addr));
}
__device__ __forceinline__ void mma_bf16(float* c, const unsigned* a,
                                         unsigned b0, unsigned b1) {
    asm volatile(
        "mma.sync.aligned.m16n8k16.row.col.f32.bf16.bf16.f32 "
        "{%0,%1,%2,%3}, {%4,%5,%6,%7}, {%8,%9}, {%0,%1,%2,%3};"
        : "+f"(c[0]), "+f"(c[1]), "+f"(c[2]), "+f"(c[3])
        : "r"(a[0]), "r"(a[1]), "r"(a[2]), "r"(a[3]), "r"(b0), "r"(b1));
}
__device__ __forceinline__ void mma_tf32(float* c, const unsigned* a,
                                         unsigned b0, unsigned b1) {
    asm volatile(
        "mma.sync.aligned.m16n8k8.row.col.f32.tf32.tf32.f32 "
        "{%0,%1,%2,%3}, {%4,%5,%6,%7}, {%8,%9}, {%0,%1,%2,%3};"
        : "+f"(c[0]), "+f"(c[1]), "+f"(c[2]), "+f"(c[3])
        : "r"(a[0]), "r"(a[1]), "r"(a[2]), "r"(a[3]), "r"(b0), "r"(b1));
}
__device__ __forceinline__ float to_tf32(float x) {
    float y;
    asm("cvt.rna.tf32.f32 %0, %1;" : "=f"(y) : "f"(x));
    return y;
}

// ---------------------------------------------------------------------------
// Kernel 0: zero the column-sum accumulator (graph-replay safe).
// ---------------------------------------------------------------------------
__global__ void zero_c_kernel() {
    g_c[blockIdx.x * 256 + threadIdx.x] = 0.0f;
}

// ---------------------------------------------------------------------------
// Kernel 1: q/k/v = LN(x^T @ W); q pre-scaled by 1/sqrt(64); all stored
// [b][f][i]; q,k rounded to tf32 precision. One warp per (b,f) row.
// ---------------------------------------------------------------------------
__device__ __forceinline__ void ln64(float& a0, float& a1, float scale) {
    float s = a0 + a1;
    #pragma unroll
    for (int o = 16; o; o >>= 1) s += __shfl_xor_sync(0xffffffffu, s, o);
    float mu = s * (1.0f / 64.0f);
    float t0 = a0 - mu, t1 = a1 - mu;
    float ss = t0 * t0 + t1 * t1;
    #pragma unroll
    for (int o = 16; o; o >>= 1) ss += __shfl_xor_sync(0xffffffffu, ss, o);
    float r = rsqrtf(ss * (1.0f / 64.0f) + 1e-5f) * scale;
    a0 = t0 * r; a1 = t1 * r;
}

__global__ void __launch_bounds__(256) qkv_ln_kernel(
    const float* __restrict__ x,
    const float* __restrict__ Wq,
    const float* __restrict__ Wk,
    const float* __restrict__ Wv)
{
    __shared__ float sW[3 * D_ * I_];
    int tid = threadIdx.x;
    for (int i = tid; i < D_ * I_; i += 256) {
        sW[i]               = Wq[i];
        sW[D_ * I_ + i]     = Wk[i];
        sW[2 * D_ * I_ + i] = Wv[i];
    }
    __syncthreads();

    int warp = tid >> 5, lane = tid & 31;
    int row = blockIdx.x * 8 + warp;
    int b = row >> 12, f = row & (F_ - 1);

    const float* xp = x + (size_t)b * D_ * F_ + f;
    float xv0 = xp[(size_t)lane * F_];
    float xv1 = (lane < D_ - 32) ? xp[(size_t)(lane + 32) * F_] : 0.0f;

    float q0 = 0, q1 = 0, k0 = 0, k1 = 0, v0 = 0, v1 = 0;
    #pragma unroll
    for (int d = 0; d < D_; ++d) {
        float xd = (d < 32) ? __shfl_sync(0xffffffffu, xv0, d)
                            : __shfl_sync(0xffffffffu, xv1, d - 32);
        const float* w = sW + d * I_;
        q0 += xd * w[lane];                  q1 += xd * w[lane + 32];
        k0 += xd * w[D_ * I_ + lane];        k1 += xd * w[D_ * I_ + lane + 32];
        v0 += xd * w[2 * D_ * I_ + lane];    v1 += xd * w[2 * D_ * I_ + lane + 32];
    }

    ln64(q0, q1, 0.125f);
    ln64(k0, k1, 1.0f);
    ln64(v0, v1, 1.0f);

    size_t ov = (size_t)row * I_ + lane;
    g_q[ov] = to_tf32(q0);  g_q[ov + 32] = to_tf32(q1);
    g_k[ov] = to_tf32(k0);  g_k[ov + 32] = to_tf32(k1);
    g_v[ov] = v0;           g_v[ov + 32] = v1;
}

// ---------------------------------------------------------------------------
// Kernel 2: S[m][n] = q[m]·k[n] via tf32 mma.sync (m16n8k8).
// 128m x 128n block, 256 thr, warp tile 64m x 32n, K=64 one-shot in smem.
// A tile q[128][64], B tile k[128][64]: 256B swizzled rows, ldmatrix frags.
// Epilogue: P=exp(S) bf16 [m][n] + column sums via shfl + smem + atomics.
// ---------------------------------------------------------------------------
#define QK_SA   0u
#define QK_SB   32768u
#define QK_SCOL 65536
#define QK_SMEM (65536 + 512)

__global__ void __launch_bounds__(256) qk_hmma_kernel() {
    extern __shared__ char sm[];
    unsigned sb = smem_u32(sm);
    float* scol = (float*)(sm + QK_SCOL);

    int tid = threadIdx.x, lane = tid & 31, w = tid >> 5;
    int m0 = blockIdx.x * 128, n0 = blockIdx.y * 128, b = blockIdx.z;

    const float* qv = g_q + ((size_t)b * F_ + m0) * I_;
    const float* kv = g_k + ((size_t)b * F_ + n0) * I_;

    if (tid < 128) scol[tid] = 0.0f;
    #pragma unroll
    for (int j = 0; j < 8; ++j) {
        int idx = tid + j * 256;
        int r = idx >> 4, c = idx & 15;
        unsigned off = SW256B((unsigned)(r * 256 + c * 16));
        cp_async16(sb + QK_SA + off, qv + r * 64 + c * 4);
        cp_async16(sb + QK_SB + off, kv + r * 64 + c * 4);
    }
    cp_commit();
    cp_wait<0>();
    __syncthreads();

    int wm = w & 1, wn = w >> 1;             // 2 x 4 warp grid
    int lrow = (lane & 7) + ((lane >> 3) & 1) * 8;
    int lch  = lane >> 4;                    // 0/1: k-chunk select

    float acc[4][4][4] = {};

    #pragma unroll
    for (int ks = 0; ks < 8; ++ks) {
        unsigned a[4][4], bB[2][4];
        #pragma unroll
        for (int mf = 0; mf < 4; ++mf) {
            unsigned row = (unsigned)(wm * 64 + mf * 16 + lrow);
            ldm_x4(a[mf], sb + QK_SA + SW256B(row * 256 + (ks * 2 + lch) * 16));
        }
        #pragma unroll
        for (int np = 0; np < 2; ++np) {
            unsigned row = (unsigned)(wn * 32 + np * 16 + lrow);
            ldm_x4(bB[np], sb + QK_SB + SW256B(row * 256 + (ks * 2 + lch) * 16));
        }
        #pragma unroll
        for (int mf = 0; mf < 4; ++mf)
            #pragma unroll
            for (int nf = 0; nf < 4; ++nf) {
                int np = nf >> 1, s = nf & 1;
                mma_tf32(acc[mf][nf], a[mf], bB[np][s], bB[np][s + 2]);
            }
    }

    // Epilogue
    __nv_bfloat16* Pp = g_P + ((size_t)b << 24);
    int r0 = lane >> 2, c2 = (lane & 3) * 2;
    float cp0[4] = {}, cp1[4] = {};
    #pragma unroll
    for (int mf = 0; mf < 4; ++mf) {
        int mr = m0 + wm * 64 + mf * 16 + r0;
        #pragma unroll
        for (int nf = 0; nf < 4; ++nf) {
            int nn = n0 + wn * 32 + nf * 8 + c2;
            float e0 = __expf(acc[mf][nf][0]);
            float e1 = __expf(acc[mf][nf][1]);
            float e2 = __expf(acc[mf][nf][2]);
            float e3 = __expf(acc[mf][nf][3]);
            cp0[nf] += e0 + e2;
            cp1[nf] += e1 + e3;
            *(__nv_bfloat162*)(Pp + (size_t)mr * F_ + nn) = __floats2bfloat162_rn(e0, e1);
            *(__nv_bfloat162*)(Pp + (size_t)(mr + 8) * F_ + nn) = __floats2bfloat162_rn(e2, e3);
        }
    }
    #pragma unroll
    for (int o = 4; o <= 16; o <<= 1)
        #pragma unroll
        for (int nf = 0; nf < 4; ++nf) {
            cp0[nf] += __shfl_xor_sync(0xffffffffu, cp0[nf], o);
            cp1[nf] += __shfl_xor_sync(0xffffffffu, cp1[nf], o);
        }
    if (lane < 4) {
        #pragma unroll
        for (int nf = 0; nf < 4; ++nf) {
            atomicAdd(&scol[wn * 32 + nf * 8 + lane * 2],     cp0[nf]);
            atomicAdd(&scol[wn * 32 + nf * 8 + lane * 2 + 1], cp1[nf]);
        }
    }
    __syncthreads();
    if (tid < 128) atomicAdd(&g_c[b * F_ + n0 + tid], scol[tid]);
}

// ---------------------------------------------------------------------------
// Kernel 3: g_vs[b][n][i] = bf16( v[b][n][i] / c[b][n] ). 8 elems/thread.
// ---------------------------------------------------------------------------
__global__ void __launch_bounds__(256) vscale_kernel() {
    size_t e = ((size_t)blockIdx.x * 256 + threadIdx.x) * 8;
    int row = (int)(e >> 6);             // b*F + n
    float rc = 1.0f / g_c[row];

    const float* vp = g_v + e;
    float4 v0 = *(const float4*)vp;
    float4 v1 = *(const float4*)(vp + 4);

    __nv_bfloat162 h[4];
    h[0] = __floats2bfloat162_rn(v0.x * rc, v0.y * rc);
    h[1] = __floats2bfloat162_rn(v0.z * rc, v0.w * rc);
    h[2] = __floats2bfloat162_rn(v1.x * rc, v1.y * rc);
    h[3] = __floats2bfloat162_rn(v1.z * rc, v1.w * rc);
    *(uint4*)(g_vs + e) = *(uint4*)h;
}

// ---------------------------------------------------------------------------
// Kernel 4: out[m][i] = sum_n P[m][n] * Vs[n][i]  via HMMA mma.sync bf16.
// Block: 256 thr, tile 256(m) x 64(i), K=4096 in 64 chunks of 64.
// cp.async double-buffered smem (SW128-swizzled 128B rows), ldmatrix operands.
// ---------------------------------------------------------------------------
#define AV_P0   0u
#define AV_PSZ  32768u
#define AV_V0   65536u
#define AV_VSZ  8192u
#define AV_SMEM 81920

__global__ void __launch_bounds__(256) av_hmma_kernel(float* __restrict__ out) {
    extern __shared__ char sm[];
    unsigned sb = smem_u32(sm);

    int tid = threadIdx.x, lane = tid & 31, w = tid >> 5;
    int m0 = blockIdx.x * 256;
    int b  = blockIdx.y;

    const __nv_bfloat16* Pb = g_P  + ((size_t)b << 24);
    const __nv_bfloat16* Vb = g_vs + (size_t)b * F_ * I_;

    int pr  = tid >> 3;            // base row
    int pc  = (tid & 7) << 4;      // byte col within 128B row

    float acc[2][8][4] = {};

    // ---- fill chunk 0 ----
    {
        #pragma unroll
        for (int j = 0; j < 8; ++j) {
            int r = pr + j * 32;
            cp_async16(sb + AV_P0 + SW128B((unsigned)(r * 128 + pc)),
                       Pb + (size_t)(m0 + r) * F_ + (pc >> 1));
        }
        #pragma unroll
        for (int j = 0; j < 2; ++j) {
            int r = pr + j * 32;
            cp_async16(sb + AV_V0 + SW128B((unsigned)(r * 128 + pc)),
                       Vb + (size_t)r * I_ + (pc >> 1));
        }
        cp_commit();
    }

    unsigned a_row = (unsigned)((w * 32 + (lane & 15)) * 128 + ((lane >> 4) << 4));
    unsigned b_row = (unsigned)(((lane & 15)) * 128 + ((lane >> 4) << 4));

    for (int t = 0; t < F_ / 64; ++t) {
        unsigned pbuf = sb + AV_P0 + (t & 1) * AV_PSZ;
        unsigned vbuf = sb + AV_V0 + (t & 1) * AV_VSZ;

        if (t < F_ / 64 - 1) {
            int kc = (t + 1) * 64;
            unsigned pd = sb + AV_P0 + ((t + 1) & 1) * AV_PSZ;
            unsigned vd = sb + AV_V0 + ((t + 1) & 1) * AV_VSZ;
            #pragma unroll
            for (int j = 0; j < 8; ++j) {
                int r = pr + j * 32;
                cp_async16(pd + SW128B((unsigned)(r * 128 + pc)),
                           Pb + (size_t)(m0 + r) * F_ + kc + (pc >> 1));
            }
            #pragma unroll
            for (int j = 0; j < 2; ++j) {
                int r = pr + j * 32;
                cp_async16(vd + SW128B((unsigned)(r * 128 + pc)),
                           Vb + (size_t)(kc + r) * I_ + (pc >> 1));
            }
            cp_commit();
            cp_wait<1>();
        } else {
            cp_wait<0>();
        }
        __syncthreads();

        #pragma unroll
        for (int s = 0; s < 4; ++s) {
            unsigned a[2][4], bv[4][4];
            ldm_x4(a[0], pbuf + SW128B(a_row + s * 32));
            ldm_x4(a[1], pbuf + SW128B(a_row + 2048 + s * 32));
            #pragma unroll
            for (int p = 0; p < 4; ++p)
                ldm_x4_t(bv[p], vbuf + SW128B(b_row + s * 2048 + p * 32));

            #pragma unroll
            for (int mt = 0; mt < 2; ++mt)
                #pragma unroll
                for (int p = 0; p < 4; ++p) {
                    mma_bf16(acc[mt][2 * p],     a[mt], bv[p][0], bv[p][1]);
                    mma_bf16(acc[mt][2 * p + 1], a[mt], bv[p][2], bv[p][3]);
                }
        }
        __syncthreads();
    }

    int mrow = m0 + w * 32 + (lane >> 2);
    int col  = (lane & 3) * 2;
    #pragma unroll
    for (int mt = 0; mt < 2; ++mt) {
        float* o0 = out + ((size_t)b * F_ + mrow + mt * 16) * I_ + col;
        float* o1 = o0 + 8 * I_;
        #pragma unroll
        for (int it = 0; it < 8; ++it) {
            *(float2*)(o0 + it * 8) = make_float2(acc[mt][it][0], acc[mt][it][1]);
            *(float2*)(o1 + it * 8) = make_float2(acc[mt][it][2], acc[mt][it][3]);
        }
    }
}

// ---------------------------------------------------------------------------
extern "C" void kernel_launch(void* const* d_in, const int* in_sizes, int n_in,
                              void* d_out, int out_size)
{
    const float* x  = (const float*)d_in[0];
    const float* Wq = (const float*)d_in[1];
    const float* Wk = (const float*)d_in[2];
    const float* Wv = (const float*)d_in[3];
    float* out = (float*)d_out;

    static bool attr_done = false;
    if (!attr_done) {
        cudaFuncSetAttribute(qk_hmma_kernel,
                             cudaFuncAttributeMaxDynamicSharedMemorySize, QK_SMEM);
        cudaFuncSetAttribute(av_hmma_kernel,
                             cudaFuncAttributeMaxDynamicSharedMemorySize, AV_SMEM);
        attr_done = true;
    }

    zero_c_kernel<<<B_ * F_ / 256, 256>>>();
    qkv_ln_kernel<<<B_ * F_ / 8, 256>>>(x, Wq, Wk, Wv);
    qk_hmma_kernel<<<dim3(F_ / 128, F_ / 128, B_), 256, QK_SMEM>>>();
    vscale_kernel<<<B_ * F_ * I_ / (256 * 8), 256>>>();
    av_hmma_kernel<<<dim3(F_ / 256, B_), 256, AV_SMEM>>>(out);
}

// round 7
// speedup vs baseline: 4.1848x; 1.1568x over previous
#include <cuda_runtime.h>
#include <cuda_fp16.h>
#include <cstdint>
#include <math.h>

#define B_ 16
#define D_ 37
#define F_ 4096
#define I_ 64

// ---- scratch (static device globals: allocation-free) ----
__device__ __half g_qh[B_ * F_ * I_];                // [b][f][i], LN'd, /8, fp16
__device__ __half g_kh[B_ * F_ * I_];                // [b][f][i], LN'd, fp16
__device__ float  g_v [B_ * F_ * I_];                // [b][f][i], LN'd fp32
__device__ float  g_c [B_ * F_];                     // c[n] = sum_m exp(S[m][n])
__device__ __half g_P [(size_t)B_ * F_ * F_];        // P[b][m][n] = exp(S), fp16, n contig
__device__ __half g_vs[B_ * F_ * I_];                // Vs[b][n][i] = v[n][i]/c[n], fp16

#define SW128B(o) ((o) ^ (((o) >> 3) & 0x70))

// ======================= PTX helpers (arch-generic, sm_80+) ==================
__device__ __forceinline__ unsigned smem_u32(const void* p) {
    unsigned a;
    asm("{ .reg .u64 t; cvta.to.shared.u64 t, %1; cvt.u32.u64 %0, t; }"
        : "=r"(a) : "l"(p));
    return a;
}
__device__ __forceinline__ void cp_async16(unsigned dst, const void* src) {
    asm volatile("cp.async.cg.shared.global [%0], [%1], 16;" :: "r"(dst), "l"(src));
}
__device__ __forceinline__ void cp_commit() {
    asm volatile("cp.async.commit_group;" ::: "memory");
}
template <int N>
__device__ __forceinline__ void cp_wait() {
    asm volatile("cp.async.wait_group %0;" :: "n"(N) : "memory");
}
__device__ __forceinline__ void ldm_x4(unsigned* r, unsigned addr) {
    asm volatile("ldmatrix.sync.aligned.m8n8.x4.shared.b16 {%0,%1,%2,%3}, [%4];"
                 : "=r"(r[0]), "=r"(r[1]), "=r"(r[2]), "=r"(r[3]) : "r"(addr));
}
__device__ __forceinline__ void ldm_x4_t(unsigned* r, unsigned addr) {
    asm volatile("ldmatrix.sync.aligned.m8n8.x4.trans.shared.b16 {%0,%1,%2,%3}, [%4];"
                 : "=r"(r[0]), "=r"(r[1]), "=r"(r[2]), "=r"(r[3]) : "r"(addr));
}
__device__ __forceinline__ void mma_f16(float* c, const unsigned* a,
                                        unsigned b0, unsigned b1) {
    asm volatile(
        "mma.sync.aligned.m16n8k16.row.col.f32.f16.f16.f32 "
        "{%0,%1,%2,%3}, {%4,%5,%6,%7}, {%8,%9}, {%0,%1,%2,%3};"
        : "+f"(c[0]), "+f"(c[1]), "+f"(c[2]), "+f"(c[3])
        : "r"(a[0]), "r"(a[1]), "r"(a[2]), "r"(a[3]), "r"(b0), "r"(b1));
}

// ---------------------------------------------------------------------------
// Kernel 0: zero the column-sum accumulator (graph-replay safe).
// ---------------------------------------------------------------------------
__global__ void zero_c_kernel() {
    g_c[blockIdx.x * 256 + threadIdx.x] = 0.0f;
}

// ---------------------------------------------------------------------------
// Kernel 1: q/k/v = LN(x^T @ W); q pre-scaled by 1/sqrt(64); all stored
// [b][f][i]; q,k in fp16. One warp per (b,f) row.
// ---------------------------------------------------------------------------
__device__ __forceinline__ void ln64(float& a0, float& a1, float scale) {
    float s = a0 + a1;
    #pragma unroll
    for (int o = 16; o; o >>= 1) s += __shfl_xor_sync(0xffffffffu, s, o);
    float mu = s * (1.0f / 64.0f);
    float t0 = a0 - mu, t1 = a1 - mu;
    float ss = t0 * t0 + t1 * t1;
    #pragma unroll
    for (int o = 16; o; o >>= 1) ss += __shfl_xor_sync(0xffffffffu, ss, o);
    float r = rsqrtf(ss * (1.0f / 64.0f) + 1e-5f) * scale;
    a0 = t0 * r; a1 = t1 * r;
}

__global__ void __launch_bounds__(256) qkv_ln_kernel(
    const float* __restrict__ x,
    const float* __restrict__ Wq,
    const float* __restrict__ Wk,
    const float* __restrict__ Wv)
{
    __shared__ float sW[3 * D_ * I_];
    int tid = threadIdx.x;
    for (int i = tid; i < D_ * I_; i += 256) {
        sW[i]               = Wq[i];
        sW[D_ * I_ + i]     = Wk[i];
        sW[2 * D_ * I_ + i] = Wv[i];
    }
    __syncthreads();

    int warp = tid >> 5, lane = tid & 31;
    int row = blockIdx.x * 8 + warp;
    int b = row >> 12, f = row & (F_ - 1);

    const float* xp = x + (size_t)b * D_ * F_ + f;
    float xv0 = xp[(size_t)lane * F_];
    float xv1 = (lane < D_ - 32) ? xp[(size_t)(lane + 32) * F_] : 0.0f;

    float q0 = 0, q1 = 0, k0 = 0, k1 = 0, v0 = 0, v1 = 0;
    #pragma unroll
    for (int d = 0; d < D_; ++d) {
        float xd = (d < 32) ? __shfl_sync(0xffffffffu, xv0, d)
                            : __shfl_sync(0xffffffffu, xv1, d - 32);
        const float* w = sW + d * I_;
        q0 += xd * w[lane];                  q1 += xd * w[lane + 32];
        k0 += xd * w[D_ * I_ + lane];        k1 += xd * w[D_ * I_ + lane + 32];
        v0 += xd * w[2 * D_ * I_ + lane];    v1 += xd * w[2 * D_ * I_ + lane + 32];
    }

    ln64(q0, q1, 0.125f);
    ln64(k0, k1, 1.0f);
    ln64(v0, v1, 1.0f);

    size_t ov = (size_t)row * I_ + lane;
    g_qh[ov] = __float2half_rn(q0);  g_qh[ov + 32] = __float2half_rn(q1);
    g_kh[ov] = __float2half_rn(k0);  g_kh[ov + 32] = __float2half_rn(k1);
    g_v [ov] = v0;                   g_v [ov + 32] = v1;
}

// ---------------------------------------------------------------------------
// Kernel 2: S[m][n] = q[m]·k[n] via fp16 mma.sync (m16n8k16).
// 128m x 128n block, 256 thr, warp tile 64m x 32n, K=64 one-shot in smem.
// Tiles are 128B rows (64 halves) SW128-swizzled; ldmatrix non-trans frags.
// Epilogue: P=exp(S) fp16 [m][n] + column sums via shfl + smem + atomics.
// ---------------------------------------------------------------------------
#define QK_SA   0u
#define QK_SB   16384u
#define QK_SCOL 32768
#define QK_SMEM (32768 + 512)

__global__ void __launch_bounds__(256) qk_hmma_kernel() {
    extern __shared__ char sm[];
    unsigned sb = smem_u32(sm);
    float* scol = (float*)(sm + QK_SCOL);

    int tid = threadIdx.x, lane = tid & 31, w = tid >> 5;
    int m0 = blockIdx.x * 128, n0 = blockIdx.y * 128, b = blockIdx.z;

    const __half* qv = g_qh + ((size_t)b * F_ + m0) * I_;
    const __half* kv = g_kh + ((size_t)b * F_ + n0) * I_;

    if (tid < 128) scol[tid] = 0.0f;
    #pragma unroll
    for (int j = 0; j < 4; ++j) {
        int idx = tid + j * 256;
        int r = idx >> 3, c = idx & 7;
        unsigned off = SW128B((unsigned)(r * 128 + c * 16));
        cp_async16(sb + QK_SA + off, qv + r * 64 + c * 8);
        cp_async16(sb + QK_SB + off, kv + r * 64 + c * 8);
    }
    cp_commit();
    cp_wait<0>();
    __syncthreads();

    int wm = w & 1, wn = w >> 1;             // 2 x 4 warp grid
    // A frag rows: m tile; koff by lane>>4
    unsigned a_lrow = (unsigned)((lane & 7) + ((lane >> 3) & 1) * 8);
    unsigned a_koff = (unsigned)((lane >> 4) << 4);
    // B frag rows: n tile; koff by (lane>>3)&1
    unsigned b_lrow = (unsigned)((lane & 7) + ((lane >> 4) << 3));
    unsigned b_koff = (unsigned)(((lane >> 3) & 1) << 4);

    float acc[4][4][4] = {};

    #pragma unroll
    for (int ks = 0; ks < 4; ++ks) {
        unsigned a[4][4], bB[2][4];
        #pragma unroll
        for (int mf = 0; mf < 4; ++mf) {
            unsigned row = (unsigned)(wm * 64 + mf * 16) + a_lrow;
            ldm_x4(a[mf], sb + QK_SA + SW128B(row * 128 + a_koff + ks * 32));
        }
        #pragma unroll
        for (int np = 0; np < 2; ++np) {
            unsigned row = (unsigned)(wn * 32 + np * 16) + b_lrow;
            ldm_x4(bB[np], sb + QK_SB + SW128B(row * 128 + b_koff + ks * 32));
        }
        #pragma unroll
        for (int mf = 0; mf < 4; ++mf)
            #pragma unroll
            for (int nf = 0; nf < 4; ++nf) {
                int np = nf >> 1, s = nf & 1;
                mma_f16(acc[mf][nf], a[mf], bB[np][2 * s], bB[np][2 * s + 1]);
            }
    }

    // Epilogue
    __half* Pp = g_P + ((size_t)b << 24);
    int r0 = lane >> 2, c2 = (lane & 3) * 2;
    float cp0[4] = {}, cp1[4] = {};
    #pragma unroll
    for (int mf = 0; mf < 4; ++mf) {
        int mr = m0 + wm * 64 + mf * 16 + r0;
        #pragma unroll
        for (int nf = 0; nf < 4; ++nf) {
            int nn = n0 + wn * 32 + nf * 8 + c2;
            float e0 = __expf(acc[mf][nf][0]);
            float e1 = __expf(acc[mf][nf][1]);
            float e2 = __expf(acc[mf][nf][2]);
            float e3 = __expf(acc[mf][nf][3]);
            cp0[nf] += e0 + e2;
            cp1[nf] += e1 + e3;
            *(__half2*)(Pp + (size_t)mr * F_ + nn)       = __floats2half2_rn(e0, e1);
            *(__half2*)(Pp + (size_t)(mr + 8) * F_ + nn) = __floats2half2_rn(e2, e3);
        }
    }
    #pragma unroll
    for (int o = 4; o <= 16; o <<= 1)
        #pragma unroll
        for (int nf = 0; nf < 4; ++nf) {
            cp0[nf] += __shfl_xor_sync(0xffffffffu, cp0[nf], o);
            cp1[nf] += __shfl_xor_sync(0xffffffffu, cp1[nf], o);
        }
    if (lane < 4) {
        #pragma unroll
        for (int nf = 0; nf < 4; ++nf) {
            atomicAdd(&scol[wn * 32 + nf * 8 + lane * 2],     cp0[nf]);
            atomicAdd(&scol[wn * 32 + nf * 8 + lane * 2 + 1], cp1[nf]);
        }
    }
    __syncthreads();
    if (tid < 128) atomicAdd(&g_c[b * F_ + n0 + tid], scol[tid]);
}

// ---------------------------------------------------------------------------
// Kernel 3: g_vs[b][n][i] = fp16( v[b][n][i] / c[b][n] ). 8 elems/thread.
// ---------------------------------------------------------------------------
__global__ void __launch_bounds__(256) vscale_kernel() {
    size_t e = ((size_t)blockIdx.x * 256 + threadIdx.x) * 8;
    int row = (int)(e >> 6);             // b*F + n
    float rc = 1.0f / g_c[row];

    const float* vp = g_v + e;
    float4 v0 = *(const float4*)vp;
    float4 v1 = *(const float4*)(vp + 4);

    __half2 h[4];
    h[0] = __floats2half2_rn(v0.x * rc, v0.y * rc);
    h[1] = __floats2half2_rn(v0.z * rc, v0.w * rc);
    h[2] = __floats2half2_rn(v1.x * rc, v1.y * rc);
    h[3] = __floats2half2_rn(v1.z * rc, v1.w * rc);
    *(uint4*)(g_vs + e) = *(uint4*)h;
}

// ---------------------------------------------------------------------------
// Kernel 4: out[m][i] = sum_n P[m][n] * Vs[n][i]  via fp16 mma.sync.
// Block: 256 thr, tile 256(m) x 64(i), K=4096 in 64 chunks of 64.
// cp.async double-buffered smem (SW128-swizzled 128B rows), ldmatrix operands.
// ---------------------------------------------------------------------------
#define AV_P0   0u
#define AV_PSZ  32768u
#define AV_V0   65536u
#define AV_VSZ  8192u
#define AV_SMEM 81920

__global__ void __launch_bounds__(256) av_hmma_kernel(float* __restrict__ out) {
    extern __shared__ char sm[];
    unsigned sb = smem_u32(sm);

    int tid = threadIdx.x, lane = tid & 31, w = tid >> 5;
    int m0 = blockIdx.x * 256;
    int b  = blockIdx.y;

    const __half* Pb = g_P  + ((size_t)b << 24);
    const __half* Vb = g_vs + (size_t)b * F_ * I_;

    int pr  = tid >> 3;            // base row
    int pc  = (tid & 7) << 4;      // byte col within 128B row

    float acc[2][8][4] = {};

    // ---- fill chunk 0 ----
    {
        #pragma unroll
        for (int j = 0; j < 8; ++j) {
            int r = pr + j * 32;
            cp_async16(sb + AV_P0 + SW128B((unsigned)(r * 128 + pc)),
                       Pb + (size_t)(m0 + r) * F_ + (pc >> 1));
        }
        #pragma unroll
        for (int j = 0; j < 2; ++j) {
            int r = pr + j * 32;
            cp_async16(sb + AV_V0 + SW128B((unsigned)(r * 128 + pc)),
                       Vb + (size_t)r * I_ + (pc >> 1));
        }
        cp_commit();
    }

    unsigned a_row = (unsigned)((w * 32 + (lane & 15)) * 128 + ((lane >> 4) << 4));
    unsigned b_row = (unsigned)(((lane & 15)) * 128 + ((lane >> 4) << 4));

    for (int t = 0; t < F_ / 64; ++t) {
        unsigned pbuf = sb + AV_P0 + (t & 1) * AV_PSZ;
        unsigned vbuf = sb + AV_V0 + (t & 1) * AV_VSZ;

        if (t < F_ / 64 - 1) {
            int kc = (t + 1) * 64;
            unsigned pd = sb + AV_P0 + ((t + 1) & 1) * AV_PSZ;
            unsigned vd = sb + AV_V0 + ((t + 1) & 1) * AV_VSZ;
            #pragma unroll
            for (int j = 0; j < 8; ++j) {
                int r = pr + j * 32;
                cp_async16(pd + SW128B((unsigned)(r * 128 + pc)),
                           Pb + (size_t)(m0 + r) * F_ + kc + (pc >> 1));
            }
            #pragma unroll
            for (int j = 0; j < 2; ++j) {
                int r = pr + j * 32;
                cp_async16(vd + SW128B((unsigned)(r * 128 + pc)),
                           Vb + (size_t)(kc + r) * I_ + (pc >> 1));
            }
            cp_commit();
            cp_wait<1>();
        } else {
            cp_wait<0>();
        }
        __syncthreads();

        #pragma unroll
        for (int s = 0; s < 4; ++s) {
            unsigned a[2][4], bv[4][4];
            ldm_x4(a[0], pbuf + SW128B(a_row + s * 32));
            ldm_x4(a[1], pbuf + SW128B(a_row + 2048 + s * 32));
            #pragma unroll
            for (int p = 0; p < 4; ++p)
                ldm_x4_t(bv[p], vbuf + SW128B(b_row + s * 2048 + p * 32));

            #pragma unroll
            for (int mt = 0; mt < 2; ++mt)
                #pragma unroll
                for (int p = 0; p < 4; ++p) {
                    mma_f16(acc[mt][2 * p],     a[mt], bv[p][0], bv[p][1]);
                    mma_f16(acc[mt][2 * p + 1], a[mt], bv[p][2], bv[p][3]);
                }
        }
        __syncthreads();
    }

    int mrow = m0 + w * 32 + (lane >> 2);
    int col  = (lane & 3) * 2;
    #pragma unroll
    for (int mt = 0; mt < 2; ++mt) {
        float* o0 = out + ((size_t)b * F_ + mrow + mt * 16) * I_ + col;
        float* o1 = o0 + 8 * I_;
        #pragma unroll
        for (int it = 0; it < 8; ++it) {
            *(float2*)(o0 + it * 8) = make_float2(acc[mt][it][0], acc[mt][it][1]);
            *(float2*)(o1 + it * 8) = make_float2(acc[mt][it][2], acc[mt][it][3]);
        }
    }
}

// ---------------------------------------------------------------------------
extern "C" void kernel_launch(void* const* d_in, const int* in_sizes, int n_in,
                              void* d_out, int out_size)
{
    const float* x  = (const float*)d_in[0];
    const float* Wq = (const float*)d_in[1];
    const float* Wk = (const float*)d_in[2];
    const float* Wv = (const float*)d_in[3];
    float* out = (float*)d_out;

    static bool attr_done = false;
    if (!attr_done) {
        cudaFuncSetAttribute(qk_hmma_kernel,
                             cudaFuncAttributeMaxDynamicSharedMemorySize, QK_SMEM);
        cudaFuncSetAttribute(av_hmma_kernel,
                             cudaFuncAttributeMaxDynamicSharedMemorySize, AV_SMEM);
        attr_done = true;
    }

    zero_c_kernel<<<B_ * F_ / 256, 256>>>();
    qkv_ln_kernel<<<B_ * F_ / 8, 256>>>(x, Wq, Wk, Wv);
    qk_hmma_kernel<<<dim3(F_ / 128, F_ / 128, B_), 256, QK_SMEM>>>();
    vscale_kernel<<<B_ * F_ * I_ / (256 * 8), 256>>>();
    av_hmma_kernel<<<dim3(F_ / 256, B_), 256, AV_SMEM>>>(out);
}

// round 8
// speedup vs baseline: 4.9166x; 1.1749x over previous
#include <cuda_runtime.h>
#include <cuda_fp16.h>
#include <cstdint>
#include <math.h>

#define B_ 16
#define D_ 37
#define F_ 4096
#define I_ 64

// ---- scratch (static device globals: allocation-free) ----
__device__ __half g_qh[B_ * F_ * I_];                // [b][f][i], LN'd, /8, fp16
__device__ __half g_kh[B_ * F_ * I_];                // [b][f][i], LN'd, fp16
__device__ float  g_v [B_ * F_ * I_];                // [b][f][i], LN'd fp32
__device__ float  g_c [B_ * F_];                     // c[n] = sum_m exp(S[m][n])
__device__ __half g_P [(size_t)B_ * F_ * F_];        // P[b][m][n] = exp(S), fp16, n contig
__device__ __half g_vs[B_ * F_ * I_];                // Vs[b][n][i] = v[n][i]/c[n], fp16

#define SW128B(o) ((o) ^ (((o) >> 3) & 0x70))
#define PSW(o)    ((o) ^ (((o) >> 4) & 0x70))   // swizzle for 256B rows

// ======================= PTX helpers (arch-generic, sm_80+) ==================
__device__ __forceinline__ unsigned smem_u32(const void* p) {
    unsigned a;
    asm("{ .reg .u64 t; cvta.to.shared.u64 t, %1; cvt.u32.u64 %0, t; }"
        : "=r"(a) : "l"(p));
    return a;
}
__device__ __forceinline__ void cp_async16(unsigned dst, const void* src) {
    asm volatile("cp.async.cg.shared.global [%0], [%1], 16;" :: "r"(dst), "l"(src));
}
__device__ __forceinline__ void cp_commit() {
    asm volatile("cp.async.commit_group;" ::: "memory");
}
template <int N>
__device__ __forceinline__ void cp_wait() {
    asm volatile("cp.async.wait_group %0;" :: "n"(N) : "memory");
}
__device__ __forceinline__ void ldm_x4(unsigned* r, unsigned addr) {
    asm volatile("ldmatrix.sync.aligned.m8n8.x4.shared.b16 {%0,%1,%2,%3}, [%4];"
                 : "=r"(r[0]), "=r"(r[1]), "=r"(r[2]), "=r"(r[3]) : "r"(addr));
}
__device__ __forceinline__ void ldm_x4_t(unsigned* r, unsigned addr) {
    asm volatile("ldmatrix.sync.aligned.m8n8.x4.trans.shared.b16 {%0,%1,%2,%3}, [%4];"
                 : "=r"(r[0]), "=r"(r[1]), "=r"(r[2]), "=r"(r[3]) : "r"(addr));
}
__device__ __forceinline__ void mma_f16(float* c, const unsigned* a,
                                        unsigned b0, unsigned b1) {
    asm volatile(
        "mma.sync.aligned.m16n8k16.row.col.f32.f16.f16.f32 "
        "{%0,%1,%2,%3}, {%4,%5,%6,%7}, {%8,%9}, {%0,%1,%2,%3};"
        : "+f"(c[0]), "+f"(c[1]), "+f"(c[2]), "+f"(c[3])
        : "r"(a[0]), "r"(a[1]), "r"(a[2]), "r"(a[3]), "r"(b0), "r"(b1));
}

// ---------------------------------------------------------------------------
// Kernel 0: zero the column-sum accumulator (graph-replay safe).
// ---------------------------------------------------------------------------
__global__ void zero_c_kernel() {
    g_c[blockIdx.x * 256 + threadIdx.x] = 0.0f;
}

// ---------------------------------------------------------------------------
// Kernel 1: q/k/v = LN(x^T @ W). Block = 64 consecutive f; x tile staged in
// smem; W held in register d-chunks so each warp reads W once per 8 f's
// (8x less smem crossbar traffic than one-f-per-warp).
// ---------------------------------------------------------------------------
__device__ __forceinline__ void ln64(float& a0, float& a1, float scale) {
    float s = a0 + a1;
    #pragma unroll
    for (int o = 16; o; o >>= 1) s += __shfl_xor_sync(0xffffffffu, s, o);
    float mu = s * (1.0f / 64.0f);
    float t0 = a0 - mu, t1 = a1 - mu;
    float ss = t0 * t0 + t1 * t1;
    #pragma unroll
    for (int o = 16; o; o >>= 1) ss += __shfl_xor_sync(0xffffffffu, ss, o);
    float r = rsqrtf(ss * (1.0f / 64.0f) + 1e-5f) * scale;
    a0 = t0 * r; a1 = t1 * r;
}

__global__ void __launch_bounds__(256) qkv_ln_kernel(
    const float* __restrict__ x,
    const float* __restrict__ Wq,
    const float* __restrict__ Wk,
    const float* __restrict__ Wv)
{
    __shared__ float sW[3 * D_ * I_];   // 28416 B
    __shared__ float sx[D_ * 64];       // 9472 B
    int tid = threadIdx.x;
    int b  = blockIdx.x >> 6;
    int f0 = (blockIdx.x & 63) << 6;

    for (int i = tid; i < D_ * I_; i += 256) {
        sW[i]               = Wq[i];
        sW[D_ * I_ + i]     = Wk[i];
        sW[2 * D_ * I_ + i] = Wv[i];
    }
    for (int i = tid; i < D_ * 64; i += 256) {
        int d = i >> 6, c = i & 63;
        sx[i] = x[(size_t)b * D_ * F_ + (size_t)d * F_ + f0 + c];
    }
    __syncthreads();

    int warp = tid >> 5, lane = tid & 31;
    int fbase = warp * 8;

    float acc[8][6] = {};
    #pragma unroll
    for (int dc = 0; dc < 40; dc += 4) {
        float wr[4][6];
        #pragma unroll
        for (int dd = 0; dd < 4; ++dd) {
            int d = dc + dd;
            if (d < D_) {
                const float* w = sW + d * I_;
                wr[dd][0] = w[lane];                 wr[dd][1] = w[lane + 32];
                wr[dd][2] = w[D_ * I_ + lane];       wr[dd][3] = w[D_ * I_ + lane + 32];
                wr[dd][4] = w[2 * D_ * I_ + lane];   wr[dd][5] = w[2 * D_ * I_ + lane + 32];
            } else {
                #pragma unroll
                for (int u = 0; u < 6; ++u) wr[dd][u] = 0.0f;
            }
        }
        #pragma unroll
        for (int j = 0; j < 8; ++j) {
            #pragma unroll
            for (int dd = 0; dd < 4; ++dd) {
                int d = dc + dd;
                float xd = (d < D_) ? sx[d * 64 + fbase + j] : 0.0f;
                acc[j][0] += xd * wr[dd][0];
                acc[j][1] += xd * wr[dd][1];
                acc[j][2] += xd * wr[dd][2];
                acc[j][3] += xd * wr[dd][3];
                acc[j][4] += xd * wr[dd][4];
                acc[j][5] += xd * wr[dd][5];
            }
        }
    }

    #pragma unroll
    for (int j = 0; j < 8; ++j) {
        ln64(acc[j][0], acc[j][1], 0.125f);
        ln64(acc[j][2], acc[j][3], 1.0f);
        ln64(acc[j][4], acc[j][5], 1.0f);
        size_t ov = ((size_t)b * F_ + f0 + fbase + j) * I_ + lane;
        g_qh[ov] = __float2half_rn(acc[j][0]); g_qh[ov + 32] = __float2half_rn(acc[j][1]);
        g_kh[ov] = __float2half_rn(acc[j][2]); g_kh[ov + 32] = __float2half_rn(acc[j][3]);
        g_v [ov] = acc[j][4];                  g_v [ov + 32] = acc[j][5];
    }
}

// ---------------------------------------------------------------------------
// Kernel 2: S[m][n] = q[m]·k[n] via fp16 mma.sync (m16n8k16).
// 128m x 128n block, 256 thr, warp tile 64m x 32n, K=64 one-shot in smem.
// Epilogue: exp -> smem-staged P tile (swizzled 256B rows) -> coalesced
// 128B global writes; column sums via shfl + smem + atomics.
// ---------------------------------------------------------------------------
#define QK_SA   0u
#define QK_SB   16384u
#define QK_SCOL 32768
#define QK_SMEM (32768 + 512)

__global__ void __launch_bounds__(256) qk_hmma_kernel() {
    extern __shared__ char sm[];
    unsigned sb = smem_u32(sm);
    float* scol = (float*)(sm + QK_SCOL);

    int tid = threadIdx.x, lane = tid & 31, w = tid >> 5;
    int m0 = blockIdx.x * 128, n0 = blockIdx.y * 128, b = blockIdx.z;

    const __half* qv = g_qh + ((size_t)b * F_ + m0) * I_;
    const __half* kv = g_kh + ((size_t)b * F_ + n0) * I_;

    if (tid < 128) scol[tid] = 0.0f;
    #pragma unroll
    for (int j = 0; j < 4; ++j) {
        int idx = tid + j * 256;
        int r = idx >> 3, c = idx & 7;
        unsigned off = SW128B((unsigned)(r * 128 + c * 16));
        cp_async16(sb + QK_SA + off, qv + r * 64 + c * 8);
        cp_async16(sb + QK_SB + off, kv + r * 64 + c * 8);
    }
    cp_commit();
    cp_wait<0>();
    __syncthreads();

    int wm = w & 1, wn = w >> 1;             // 2 x 4 warp grid
    unsigned a_lrow = (unsigned)((lane & 7) + ((lane >> 3) & 1) * 8);
    unsigned a_koff = (unsigned)((lane >> 4) << 4);
    unsigned b_lrow = (unsigned)((lane & 7) + ((lane >> 4) << 3));
    unsigned b_koff = (unsigned)(((lane >> 3) & 1) << 4);

    float acc[4][4][4] = {};

    #pragma unroll
    for (int ks = 0; ks < 4; ++ks) {
        unsigned a[4][4], bB[2][4];
        #pragma unroll
        for (int mf = 0; mf < 4; ++mf) {
            unsigned row = (unsigned)(wm * 64 + mf * 16) + a_lrow;
            ldm_x4(a[mf], sb + QK_SA + SW128B(row * 128 + a_koff + ks * 32));
        }
        #pragma unroll
        for (int np = 0; np < 2; ++np) {
            unsigned row = (unsigned)(wn * 32 + np * 16) + b_lrow;
            ldm_x4(bB[np], sb + QK_SB + SW128B(row * 128 + b_koff + ks * 32));
        }
        #pragma unroll
        for (int mf = 0; mf < 4; ++mf)
            #pragma unroll
            for (int nf = 0; nf < 4; ++nf) {
                int np = nf >> 1, s = nf & 1;
                mma_f16(acc[mf][nf], a[mf], bB[np][2 * s], bB[np][2 * s + 1]);
            }
    }

    // ---- epilogue: exp + colsums, stage P in smem, coalesced global write ----
    __syncthreads();   // all warps done reading the q/k tiles

    int r0 = lane >> 2, c2 = (lane & 3) * 2;
    float cp0[4] = {}, cp1[4] = {};
    #pragma unroll
    for (int mf = 0; mf < 4; ++mf) {
        int rml = wm * 64 + mf * 16 + r0;       // local row in 128x128 tile
        #pragma unroll
        for (int nf = 0; nf < 4; ++nf) {
            int cnl = wn * 32 + nf * 8 + c2;    // local col
            float e0 = __expf(acc[mf][nf][0]);
            float e1 = __expf(acc[mf][nf][1]);
            float e2 = __expf(acc[mf][nf][2]);
            float e3 = __expf(acc[mf][nf][3]);
            cp0[nf] += e0 + e2;
            cp1[nf] += e1 + e3;
            unsigned o1 = (unsigned)(rml * 256 + cnl * 2);
            unsigned o2 = (unsigned)((rml + 8) * 256 + cnl * 2);
            *(__half2*)(sm + PSW(o1)) = __floats2half2_rn(e0, e1);
            *(__half2*)(sm + PSW(o2)) = __floats2half2_rn(e2, e3);
        }
    }
    #pragma unroll
    for (int o = 4; o <= 16; o <<= 1)
        #pragma unroll
        for (int nf = 0; nf < 4; ++nf) {
            cp0[nf] += __shfl_xor_sync(0xffffffffu, cp0[nf], o);
            cp1[nf] += __shfl_xor_sync(0xffffffffu, cp1[nf], o);
        }
    if (lane < 4) {
        #pragma unroll
        for (int nf = 0; nf < 4; ++nf) {
            atomicAdd(&scol[wn * 32 + nf * 8 + lane * 2],     cp0[nf]);
            atomicAdd(&scol[wn * 32 + nf * 8 + lane * 2 + 1], cp1[nf]);
        }
    }
    __syncthreads();

    __half* Pp = g_P + ((size_t)b << 24);
    #pragma unroll
    for (int i2 = 0; i2 < 8; ++i2) {
        int idx = tid + i2 * 256;
        int r = idx >> 4, c16 = idx & 15;
        uint4 val = *(uint4*)(sm + PSW((unsigned)(r * 256 + c16 * 16)));
        *(uint4*)(Pp + (size_t)(m0 + r) * F_ + n0 + c16 * 8) = val;
    }
    if (tid < 128) atomicAdd(&g_c[b * F_ + n0 + tid], scol[tid]);
}

// ---------------------------------------------------------------------------
// Kernel 3: g_vs[b][n][i] = fp16( v[b][n][i] / c[b][n] ). 8 elems/thread.
// ---------------------------------------------------------------------------
__global__ void __launch_bounds__(256) vscale_kernel() {
    size_t e = ((size_t)blockIdx.x * 256 + threadIdx.x) * 8;
    int row = (int)(e >> 6);             // b*F + n
    float rc = 1.0f / g_c[row];

    const float* vp = g_v + e;
    float4 v0 = *(const float4*)vp;
    float4 v1 = *(const float4*)(vp + 4);

    __half2 h[4];
    h[0] = __floats2half2_rn(v0.x * rc, v0.y * rc);
    h[1] = __floats2half2_rn(v0.z * rc, v0.w * rc);
    h[2] = __floats2half2_rn(v1.x * rc, v1.y * rc);
    h[3] = __floats2half2_rn(v1.z * rc, v1.w * rc);
    *(uint4*)(g_vs + e) = *(uint4*)h;
}

// ---------------------------------------------------------------------------
// Kernel 4: out[m][i] = sum_n P[m][n] * Vs[n][i]  via fp16 mma.sync.
// Block: 256 thr, tile 256(m) x 64(i), K=4096 in 64 chunks of 64.
// 3-stage cp.async ring, ONE __syncthreads per chunk.
// ---------------------------------------------------------------------------
#define AV_PST   32768u
#define AV_VBASE 98304u
#define AV_VST   8192u
#define AV_SMEM  122880

__device__ __forceinline__ void av_issue(unsigned sb, int u, int m0,
                                         const __half* Pb, const __half* Vb,
                                         int pr, int pc) {
    unsigned pd = sb + (unsigned)(u % 3) * AV_PST;
    unsigned vd = sb + AV_VBASE + (unsigned)(u % 3) * AV_VST;
    int kc = u * 64;
    #pragma unroll
    for (int j = 0; j < 8; ++j) {
        int r = pr + j * 32;
        cp_async16(pd + SW128B((unsigned)(r * 128 + pc)),
                   Pb + (size_t)(m0 + r) * F_ + kc + (pc >> 1));
    }
    #pragma unroll
    for (int j = 0; j < 2; ++j) {
        int r = pr + j * 32;
        cp_async16(vd + SW128B((unsigned)(r * 128 + pc)),
                   Vb + (size_t)(kc + r) * I_ + (pc >> 1));
    }
    cp_commit();
}

__global__ void __launch_bounds__(256) av_hmma_kernel(float* __restrict__ out) {
    extern __shared__ char sm[];
    unsigned sb = smem_u32(sm);

    int tid = threadIdx.x, lane = tid & 31, w = tid >> 5;
    int m0 = blockIdx.x * 256;
    int b  = blockIdx.y;

    const __half* Pb = g_P  + ((size_t)b << 24);
    const __half* Vb = g_vs + (size_t)b * F_ * I_;

    int pr = tid >> 3;             // base row
    int pc = (tid & 7) << 4;       // byte col within 128B row

    float acc[2][8][4] = {};

    av_issue(sb, 0, m0, Pb, Vb, pr, pc);
    av_issue(sb, 1, m0, Pb, Vb, pr, pc);

    unsigned a_row = (unsigned)((w * 32 + (lane & 15)) * 128 + ((lane >> 4) << 4));
    unsigned b_row = (unsigned)(((lane & 15)) * 128 + ((lane >> 4) << 4));

    for (int t = 0; t < F_ / 64; ++t) {
        if (t == F_ / 64 - 1) cp_wait<0>();
        else                  cp_wait<1>();
        __syncthreads();                      // data(t) visible; compute(t-1) done
        if (t + 2 < F_ / 64)
            av_issue(sb, t + 2, m0, Pb, Vb, pr, pc);

        unsigned pbuf = sb + (unsigned)(t % 3) * AV_PST;
        unsigned vbuf = sb + AV_VBASE + (unsigned)(t % 3) * AV_VST;

        #pragma unroll
        for (int s = 0; s < 4; ++s) {
            unsigned a[2][4], bv[4][4];
            ldm_x4(a[0], pbuf + SW128B(a_row + s * 32));
            ldm_x4(a[1], pbuf + SW128B(a_row + 2048 + s * 32));
            #pragma unroll
            for (int p = 0; p < 4; ++p)
                ldm_x4_t(bv[p], vbuf + SW128B(b_row + s * 2048 + p * 32));

            #pragma unroll
            for (int mt = 0; mt < 2; ++mt)
                #pragma unroll
                for (int p = 0; p < 4; ++p) {
                    mma_f16(acc[mt][2 * p],     a[mt], bv[p][0], bv[p][1]);
                    mma_f16(acc[mt][2 * p + 1], a[mt], bv[p][2], bv[p][3]);
                }
        }
    }

    int mrow = m0 + w * 32 + (lane >> 2);
    int col  = (lane & 3) * 2;
    #pragma unroll
    for (int mt = 0; mt < 2; ++mt) {
        float* o0 = out + ((size_t)b * F_ + mrow + mt * 16) * I_ + col;
        float* o1 = o0 + 8 * I_;
        #pragma unroll
        for (int it = 0; it < 8; ++it) {
            *(float2*)(o0 + it * 8) = make_float2(acc[mt][it][0], acc[mt][it][1]);
            *(float2*)(o1 + it * 8) = make_float2(acc[mt][it][2], acc[mt][it][3]);
        }
    }
}

// ---------------------------------------------------------------------------
extern "C" void kernel_launch(void* const* d_in, const int* in_sizes, int n_in,
                              void* d_out, int out_size)
{
    const float* x  = (const float*)d_in[0];
    const float* Wq = (const float*)d_in[1];
    const float* Wk = (const float*)d_in[2];
    const float* Wv = (const float*)d_in[3];
    float* out = (float*)d_out;

    static bool attr_done = false;
    if (!attr_done) {
        cudaFuncSetAttribute(qk_hmma_kernel,
                             cudaFuncAttributeMaxDynamicSharedMemorySize, QK_SMEM);
        cudaFuncSetAttribute(av_hmma_kernel,
                             cudaFuncAttributeMaxDynamicSharedMemorySize, AV_SMEM);
        attr_done = true;
    }

    zero_c_kernel<<<B_ * F_ / 256, 256>>>();
    qkv_ln_kernel<<<B_ * F_ / 64, 256>>>(x, Wq, Wk, Wv);
    qk_hmma_kernel<<<dim3(F_ / 128, F_ / 128, B_), 256, QK_SMEM>>>();
    vscale_kernel<<<B_ * F_ * I_ / (256 * 8), 256>>>();
    av_hmma_kernel<<<dim3(F_ / 256, B_), 256, AV_SMEM>>>(out);
}

// round 9
// speedup vs baseline: 5.3248x; 1.0830x over previous
#include <cuda_runtime.h>
#include <cuda_fp16.h>
#include <cstdint>
#include <math.h>

#define B_ 16
#define D_ 37
#define F_ 4096
#define I_ 64

// ---- scratch (static device globals: allocation-free) ----
__device__ __half g_qh[B_ * F_ * I_];                // [b][f][i], LN'd, *0.125*log2e, fp16
__device__ __half g_kh[B_ * F_ * I_];                // [b][f][i], LN'd, fp16
__device__ float  g_v [B_ * F_ * I_];                // [b][f][i], LN'd fp32
__device__ float  g_c [B_ * F_];                     // c[n] = sum_m exp(S[m][n])
__device__ __half g_P [(size_t)B_ * F_ * F_];        // P[b][m][n] = exp(S), fp16, n contig
__device__ __half g_vs[B_ * F_ * I_];                // Vs[b][n][i] = v[n][i]/c[n], fp16

#define SW128B(o) ((o) ^ (((o) >> 3) & 0x70))
#define PSW(o)    ((o) ^ (((o) >> 4) & 0x70))   // swizzle for 256B rows

// ======================= PTX helpers (arch-generic, sm_80+) ==================
__device__ __forceinline__ unsigned smem_u32(const void* p) {
    unsigned a;
    asm("{ .reg .u64 t; cvta.to.shared.u64 t, %1; cvt.u32.u64 %0, t; }"
        : "=r"(a) : "l"(p));
    return a;
}
__device__ __forceinline__ void cp_async16(unsigned dst, const void* src) {
    asm volatile("cp.async.cg.shared.global [%0], [%1], 16;" :: "r"(dst), "l"(src));
}
__device__ __forceinline__ void cp_commit() {
    asm volatile("cp.async.commit_group;" ::: "memory");
}
template <int N>
__device__ __forceinline__ void cp_wait() {
    asm volatile("cp.async.wait_group %0;" :: "n"(N) : "memory");
}
__device__ __forceinline__ void ldm_x4(unsigned* r, unsigned addr) {
    asm volatile("ldmatrix.sync.aligned.m8n8.x4.shared.b16 {%0,%1,%2,%3}, [%4];"
                 : "=r"(r[0]), "=r"(r[1]), "=r"(r[2]), "=r"(r[3]) : "r"(addr));
}
__device__ __forceinline__ void ldm_x4_t(unsigned* r, unsigned addr) {
    asm volatile("ldmatrix.sync.aligned.m8n8.x4.trans.shared.b16 {%0,%1,%2,%3}, [%4];"
                 : "=r"(r[0]), "=r"(r[1]), "=r"(r[2]), "=r"(r[3]) : "r"(addr));
}
__device__ __forceinline__ void mma_f16(float* c, const unsigned* a,
                                        unsigned b0, unsigned b1) {
    asm volatile(
        "mma.sync.aligned.m16n8k16.row.col.f32.f16.f16.f32 "
        "{%0,%1,%2,%3}, {%4,%5,%6,%7}, {%8,%9}, {%0,%1,%2,%3};"
        : "+f"(c[0]), "+f"(c[1]), "+f"(c[2]), "+f"(c[3])
        : "r"(a[0]), "r"(a[1]), "r"(a[2]), "r"(a[3]), "r"(b0), "r"(b1));
}
__device__ __forceinline__ float ex2(float x) {
    float y;
    asm("ex2.approx.ftz.f32 %0, %1;" : "=f"(y) : "f"(x));
    return y;
}

// ---------------------------------------------------------------------------
// Kernel 1: q/k/v = LN(x^T @ W). Block = 64 consecutive f. Also zeroes g_c.
// q scaled by 0.125*log2(e) so qk epilogue can use raw ex2.
// ---------------------------------------------------------------------------
__device__ __forceinline__ void ln64(float& a0, float& a1, float scale) {
    float s = a0 + a1;
    #pragma unroll
    for (int o = 16; o; o >>= 1) s += __shfl_xor_sync(0xffffffffu, s, o);
    float mu = s * (1.0f / 64.0f);
    float t0 = a0 - mu, t1 = a1 - mu;
    float ss = t0 * t0 + t1 * t1;
    #pragma unroll
    for (int o = 16; o; o >>= 1) ss += __shfl_xor_sync(0xffffffffu, ss, o);
    float r = rsqrtf(ss * (1.0f / 64.0f) + 1e-5f) * scale;
    a0 = t0 * r; a1 = t1 * r;
}

__global__ void __launch_bounds__(256) qkv_ln_kernel(
    const float* __restrict__ x,
    const float* __restrict__ Wq,
    const float* __restrict__ Wk,
    const float* __restrict__ Wv)
{
    __shared__ float sW[3 * D_ * I_];   // 28416 B
    __shared__ float sx[D_ * 64];       // 9472 B
    int tid = threadIdx.x;
    int b  = blockIdx.x >> 6;
    int f0 = (blockIdx.x & 63) << 6;

    if (tid < 64) g_c[b * F_ + f0 + tid] = 0.0f;   // zero colsum accumulator

    for (int i = tid; i < D_ * I_; i += 256) {
        sW[i]               = Wq[i];
        sW[D_ * I_ + i]     = Wk[i];
        sW[2 * D_ * I_ + i] = Wv[i];
    }
    for (int i = tid; i < D_ * 64; i += 256) {
        int d = i >> 6, c = i & 63;
        sx[i] = x[(size_t)b * D_ * F_ + (size_t)d * F_ + f0 + c];
    }
    __syncthreads();

    int warp = tid >> 5, lane = tid & 31;
    int fbase = warp * 8;

    float acc[8][6] = {};
    #pragma unroll
    for (int dc = 0; dc < 40; dc += 4) {
        float wr[4][6];
        #pragma unroll
        for (int dd = 0; dd < 4; ++dd) {
            int d = dc + dd;
            if (d < D_) {
                const float* w = sW + d * I_;
                wr[dd][0] = w[lane];                 wr[dd][1] = w[lane + 32];
                wr[dd][2] = w[D_ * I_ + lane];       wr[dd][3] = w[D_ * I_ + lane + 32];
                wr[dd][4] = w[2 * D_ * I_ + lane];   wr[dd][5] = w[2 * D_ * I_ + lane + 32];
            } else {
                #pragma unroll
                for (int u = 0; u < 6; ++u) wr[dd][u] = 0.0f;
            }
        }
        #pragma unroll
        for (int j = 0; j < 8; ++j) {
            #pragma unroll
            for (int dd = 0; dd < 4; ++dd) {
                int d = dc + dd;
                float xd = (d < D_) ? sx[d * 64 + fbase + j] : 0.0f;
                acc[j][0] += xd * wr[dd][0];
                acc[j][1] += xd * wr[dd][1];
                acc[j][2] += xd * wr[dd][2];
                acc[j][3] += xd * wr[dd][3];
                acc[j][4] += xd * wr[dd][4];
                acc[j][5] += xd * wr[dd][5];
            }
        }
    }

    #pragma unroll
    for (int j = 0; j < 8; ++j) {
        ln64(acc[j][0], acc[j][1], 0.18033688f);   // 0.125 * log2(e)
        ln64(acc[j][2], acc[j][3], 1.0f);
        ln64(acc[j][4], acc[j][5], 1.0f);
        size_t ov = ((size_t)b * F_ + f0 + fbase + j) * I_ + lane;
        g_qh[ov] = __float2half_rn(acc[j][0]); g_qh[ov + 32] = __float2half_rn(acc[j][1]);
        g_kh[ov] = __float2half_rn(acc[j][2]); g_kh[ov + 32] = __float2half_rn(acc[j][3]);
        g_v [ov] = acc[j][4];                  g_v [ov + 32] = acc[j][5];
    }
}

// ---------------------------------------------------------------------------
// Kernel 2: S[m][n] = q[m]·k[n] via fp16 mma.sync (m16n8k16). P = 2^S (ex2).
// 128m x 128n block, 256 thr, warp tile 64m x 32n, K=64 one-shot in smem.
// Epilogue: ex2 -> smem-staged P tile -> coalesced 128B global writes;
// column sums via shfl + smem + atomics.
// ---------------------------------------------------------------------------
#define QK_SA   0u
#define QK_SB   16384u
#define QK_SCOL 32768
#define QK_SMEM (32768 + 512)

__global__ void __launch_bounds__(256) qk_hmma_kernel() {
    extern __shared__ char sm[];
    unsigned sb = smem_u32(sm);
    float* scol = (float*)(sm + QK_SCOL);

    int tid = threadIdx.x, lane = tid & 31, w = tid >> 5;
    int m0 = blockIdx.x * 128, n0 = blockIdx.y * 128, b = blockIdx.z;

    const __half* qv = g_qh + ((size_t)b * F_ + m0) * I_;
    const __half* kv = g_kh + ((size_t)b * F_ + n0) * I_;

    if (tid < 128) scol[tid] = 0.0f;
    #pragma unroll
    for (int j = 0; j < 4; ++j) {
        int idx = tid + j * 256;
        int r = idx >> 3, c = idx & 7;
        unsigned off = SW128B((unsigned)(r * 128 + c * 16));
        cp_async16(sb + QK_SA + off, qv + r * 64 + c * 8);
        cp_async16(sb + QK_SB + off, kv + r * 64 + c * 8);
    }
    cp_commit();
    cp_wait<0>();
    __syncthreads();

    int wm = w & 1, wn = w >> 1;             // 2 x 4 warp grid
    unsigned a_lrow = (unsigned)((lane & 7) + ((lane >> 3) & 1) * 8);
    unsigned a_koff = (unsigned)((lane >> 4) << 4);
    unsigned b_lrow = (unsigned)((lane & 7) + ((lane >> 4) << 3));
    unsigned b_koff = (unsigned)(((lane >> 3) & 1) << 4);

    float acc[4][4][4] = {};

    #pragma unroll
    for (int ks = 0; ks < 4; ++ks) {
        unsigned a[4][4], bB[2][4];
        #pragma unroll
        for (int mf = 0; mf < 4; ++mf) {
            unsigned row = (unsigned)(wm * 64 + mf * 16) + a_lrow;
            ldm_x4(a[mf], sb + QK_SA + SW128B(row * 128 + a_koff + ks * 32));
        }
        #pragma unroll
        for (int np = 0; np < 2; ++np) {
            unsigned row = (unsigned)(wn * 32 + np * 16) + b_lrow;
            ldm_x4(bB[np], sb + QK_SB + SW128B(row * 128 + b_koff + ks * 32));
        }
        #pragma unroll
        for (int mf = 0; mf < 4; ++mf)
            #pragma unroll
            for (int nf = 0; nf < 4; ++nf) {
                int np = nf >> 1, s = nf & 1;
                mma_f16(acc[mf][nf], a[mf], bB[np][2 * s], bB[np][2 * s + 1]);
            }
    }

    // ---- epilogue: ex2 + colsums, stage P in smem, coalesced global write ----
    __syncthreads();   // all warps done reading the q/k tiles

    int r0 = lane >> 2, c2 = (lane & 3) * 2;
    float cp0[4] = {}, cp1[4] = {};
    #pragma unroll
    for (int mf = 0; mf < 4; ++mf) {
        int rml = wm * 64 + mf * 16 + r0;       // local row in 128x128 tile
        #pragma unroll
        for (int nf = 0; nf < 4; ++nf) {
            int cnl = wn * 32 + nf * 8 + c2;    // local col
            float e0 = ex2(acc[mf][nf][0]);
            float e1 = ex2(acc[mf][nf][1]);
            float e2 = ex2(acc[mf][nf][2]);
            float e3 = ex2(acc[mf][nf][3]);
            cp0[nf] += e0 + e2;
            cp1[nf] += e1 + e3;
            unsigned o1 = (unsigned)(rml * 256 + cnl * 2);
            unsigned o2 = (unsigned)((rml + 8) * 256 + cnl * 2);
            *(__half2*)(sm + PSW(o1)) = __floats2half2_rn(e0, e1);
            *(__half2*)(sm + PSW(o2)) = __floats2half2_rn(e2, e3);
        }
    }
    #pragma unroll
    for (int o = 4; o <= 16; o <<= 1)
        #pragma unroll
        for (int nf = 0; nf < 4; ++nf) {
            cp0[nf] += __shfl_xor_sync(0xffffffffu, cp0[nf], o);
            cp1[nf] += __shfl_xor_sync(0xffffffffu, cp1[nf], o);
        }
    if (lane < 4) {
        #pragma unroll
        for (int nf = 0; nf < 4; ++nf) {
            atomicAdd(&scol[wn * 32 + nf * 8 + lane * 2],     cp0[nf]);
            atomicAdd(&scol[wn * 32 + nf * 8 + lane * 2 + 1], cp1[nf]);
        }
    }
    __syncthreads();

    __half* Pp = g_P + ((size_t)b << 24);
    #pragma unroll
    for (int i2 = 0; i2 < 8; ++i2) {
        int idx = tid + i2 * 256;
        int r = idx >> 4, c16 = idx & 15;
        uint4 val = *(uint4*)(sm + PSW((unsigned)(r * 256 + c16 * 16)));
        *(uint4*)(Pp + (size_t)(m0 + r) * F_ + n0 + c16 * 8) = val;
    }
    if (tid < 128) atomicAdd(&g_c[b * F_ + n0 + tid], scol[tid]);
}

// ---------------------------------------------------------------------------
// Kernel 3: g_vs[b][n][i] = fp16( v[b][n][i] / c[b][n] ). 8 elems/thread.
// ---------------------------------------------------------------------------
__global__ void __launch_bounds__(256) vscale_kernel() {
    size_t e = ((size_t)blockIdx.x * 256 + threadIdx.x) * 8;
    int row = (int)(e >> 6);             // b*F + n
    float rc = 1.0f / g_c[row];

    const float* vp = g_v + e;
    float4 v0 = *(const float4*)vp;
    float4 v1 = *(const float4*)(vp + 4);

    __half2 h[4];
    h[0] = __floats2half2_rn(v0.x * rc, v0.y * rc);
    h[1] = __floats2half2_rn(v0.z * rc, v0.w * rc);
    h[2] = __floats2half2_rn(v1.x * rc, v1.y * rc);
    h[3] = __floats2half2_rn(v1.z * rc, v1.w * rc);
    *(uint4*)(g_vs + e) = *(uint4*)h;
}

// ---------------------------------------------------------------------------
// Kernel 4: out[m][i] = sum_n P[m][n] * Vs[n][i]  via fp16 mma.sync.
// 128 thr, 4 warps, CTA tile 256(m) x 64(i), warp tile 64m x 64i.
// K=4096 in 64 chunks of 64; 2-stage ping-pong (80 KB -> 2 CTA/SM ->
// all 256 CTAs in ONE wave; cross-CTA overlap hides the per-chunk syncs).
// ---------------------------------------------------------------------------
#define AV_PST   32768u
#define AV_VBASE 65536u
#define AV_VST   8192u
#define AV_SMEM  81920

__device__ __forceinline__ void av_issue(unsigned sb, int u, int m0,
                                         const __half* Pb, const __half* Vb,
                                         int tid) {
    unsigned pd = sb + (unsigned)(u & 1) * AV_PST;
    unsigned vd = sb + AV_VBASE + (unsigned)(u & 1) * AV_VST;
    int kc = u * 64;
    int r = tid >> 3, c16 = tid & 7;
    #pragma unroll
    for (int j = 0; j < 16; ++j) {
        int row = r + j * 16;
        cp_async16(pd + SW128B((unsigned)(row * 128 + c16 * 16)),
                   Pb + (size_t)(m0 + row) * F_ + kc + c16 * 8);
    }
    #pragma unroll
    for (int j = 0; j < 4; ++j) {
        int row = r + j * 16;
        cp_async16(vd + SW128B((unsigned)(row * 128 + c16 * 16)),
                   Vb + (size_t)(kc + row) * I_ + c16 * 8);
    }
    cp_commit();
}

__global__ void __launch_bounds__(128) av_hmma_kernel(float* __restrict__ out) {
    extern __shared__ char sm[];
    unsigned sb = smem_u32(sm);

    int tid = threadIdx.x, lane = tid & 31, w = tid >> 5;
    int m0 = blockIdx.x * 256;
    int b  = blockIdx.y;

    const __half* Pb = g_P  + ((size_t)b << 24);
    const __half* Vb = g_vs + (size_t)b * F_ * I_;

    float acc[4][8][4] = {};

    av_issue(sb, 0, m0, Pb, Vb, tid);
    av_issue(sb, 1, m0, Pb, Vb, tid);

    unsigned a_base = (unsigned)((w * 64 + (lane & 15)) * 128 + ((lane >> 4) << 4));
    unsigned b_base = (unsigned)((lane & 15) * 128 + ((lane >> 4) << 4));

    for (int t = 0; t < F_ / 64; ++t) {
        if (t + 1 < F_ / 64) cp_wait<1>();
        else                 cp_wait<0>();
        __syncthreads();                      // buffer t ready for all warps

        unsigned pbuf = sb + (unsigned)(t & 1) * AV_PST;
        unsigned vbuf = sb + AV_VBASE + (unsigned)(t & 1) * AV_VST;

        #pragma unroll
        for (int s = 0; s < 4; ++s) {
            unsigned a[4][4], bv[4][4];
            #pragma unroll
            for (int mf = 0; mf < 4; ++mf)
                ldm_x4(a[mf], pbuf + SW128B(a_base + mf * 2048 + s * 32));
            #pragma unroll
            for (int p = 0; p < 4; ++p)
                ldm_x4_t(bv[p], vbuf + SW128B(b_base + s * 2048 + p * 32));

            #pragma unroll
            for (int mf = 0; mf < 4; ++mf)
                #pragma unroll
                for (int p = 0; p < 4; ++p) {
                    mma_f16(acc[mf][2 * p],     a[mf], bv[p][0], bv[p][1]);
                    mma_f16(acc[mf][2 * p + 1], a[mf], bv[p][2], bv[p][3]);
                }
        }
        __syncthreads();                      // all warps done reading buffer t
        if (t + 2 < F_ / 64)
            av_issue(sb, t + 2, m0, Pb, Vb, tid);
    }

    int r0 = lane >> 2, c2 = (lane & 3) * 2;
    #pragma unroll
    for (int mf = 0; mf < 4; ++mf) {
        int mrow = m0 + w * 64 + mf * 16 + r0;
        float* o0 = out + ((size_t)b * F_ + mrow) * I_ + c2;
        float* o1 = o0 + 8 * I_;
        #pragma unroll
        for (int it = 0; it < 8; ++it) {
            *(float2*)(o0 + it * 8) = make_float2(acc[mf][it][0], acc[mf][it][1]);
            *(float2*)(o1 + it * 8) = make_float2(acc[mf][it][2], acc[mf][it][3]);
        }
    }
}

// ---------------------------------------------------------------------------
extern "C" void kernel_launch(void* const* d_in, const int* in_sizes, int n_in,
                              void* d_out, int out_size)
{
    const float* x  = (const float*)d_in[0];
    const float* Wq = (const float*)d_in[1];
    const float* Wk = (const float*)d_in[2];
    const float* Wv = (const float*)d_in[3];
    float* out = (float*)d_out;

    static bool attr_done = false;
    if (!attr_done) {
        cudaFuncSetAttribute(qk_hmma_kernel,
                             cudaFuncAttributeMaxDynamicSharedMemorySize, QK_SMEM);
        cudaFuncSetAttribute(av_hmma_kernel,
                             cudaFuncAttributeMaxDynamicSharedMemorySize, AV_SMEM);
        attr_done = true;
    }

    qkv_ln_kernel<<<B_ * F_ / 64, 256>>>(x, Wq, Wk, Wv);
    qk_hmma_kernel<<<dim3(F_ / 128, F_ / 128, B_), 256, QK_SMEM>>>();
    vscale_kernel<<<B_ * F_ * I_ / (256 * 8), 256>>>();
    av_hmma_kernel<<<dim3(F_ / 256, B_), 128, AV_SMEM>>>(out);
}

// round 10
// speedup vs baseline: 5.6422x; 1.0596x over previous
#include <cuda_runtime.h>
#include <cuda_fp16.h>
#include <cstdint>
#include <math.h>

#define B_ 16
#define D_ 37
#define F_ 4096
#define I_ 64

// ---- scratch (static device globals: allocation-free) ----
__device__ __half g_qh[B_ * F_ * I_];                // [b][f][i], LN'd, *0.125*log2e, fp16
__device__ __half g_kh[B_ * F_ * I_];                // [b][f][i], LN'd, fp16
__device__ float  g_v [B_ * F_ * I_];                // [b][f][i], LN'd fp32
__device__ float  g_c [B_ * F_];                     // c[n] = sum_m 2^(S[m][n])
__device__ __half g_P [(size_t)B_ * F_ * F_];        // P[b][m][n] = 2^S, fp16, n contig
__device__ __half g_vs[B_ * F_ * I_];                // Vs[b][n][i] = v[n][i]/c[n], fp16

#define SW128B(o) ((o) ^ (((o) >> 3) & 0x70))

// ======================= PTX helpers (arch-generic, sm_80+) ==================
__device__ __forceinline__ unsigned smem_u32(const void* p) {
    unsigned a;
    asm("{ .reg .u64 t; cvta.to.shared.u64 t, %1; cvt.u32.u64 %0, t; }"
        : "=r"(a) : "l"(p));
    return a;
}
__device__ __forceinline__ void cp_async16(unsigned dst, const void* src) {
    asm volatile("cp.async.cg.shared.global [%0], [%1], 16;" :: "r"(dst), "l"(src));
}
__device__ __forceinline__ void cp_commit() {
    asm volatile("cp.async.commit_group;" ::: "memory");
}
template <int N>
__device__ __forceinline__ void cp_wait() {
    asm volatile("cp.async.wait_group %0;" :: "n"(N) : "memory");
}
__device__ __forceinline__ void ldm_x4(unsigned* r, unsigned addr) {
    asm volatile("ldmatrix.sync.aligned.m8n8.x4.shared.b16 {%0,%1,%2,%3}, [%4];"
                 : "=r"(r[0]), "=r"(r[1]), "=r"(r[2]), "=r"(r[3]) : "r"(addr));
}
__device__ __forceinline__ void ldm_x4_t(unsigned* r, unsigned addr) {
    asm volatile("ldmatrix.sync.aligned.m8n8.x4.trans.shared.b16 {%0,%1,%2,%3}, [%4];"
                 : "=r"(r[0]), "=r"(r[1]), "=r"(r[2]), "=r"(r[3]) : "r"(addr));
}
__device__ __forceinline__ void mma_f16(float* c, const unsigned* a,
                                        unsigned b0, unsigned b1) {
    asm volatile(
        "mma.sync.aligned.m16n8k16.row.col.f32.f16.f16.f32 "
        "{%0,%1,%2,%3}, {%4,%5,%6,%7}, {%8,%9}, {%0,%1,%2,%3};"
        : "+f"(c[0]), "+f"(c[1]), "+f"(c[2]), "+f"(c[3])
        : "r"(a[0]), "r"(a[1]), "r"(a[2]), "r"(a[3]), "r"(b0), "r"(b1));
}
__device__ __forceinline__ float ex2(float x) {
    float y;
    asm("ex2.approx.ftz.f32 %0, %1;" : "=f"(y) : "f"(x));
    return y;
}

// ---------------------------------------------------------------------------
// Kernel 1: q/k/v = LN(x^T @ W). Block = 64 consecutive f. Also zeroes g_c.
// q scaled by 0.125*log2(e) so qk epilogue can use raw ex2.
// ---------------------------------------------------------------------------
__device__ __forceinline__ void ln64(float& a0, float& a1, float scale) {
    float s = a0 + a1;
    #pragma unroll
    for (int o = 16; o; o >>= 1) s += __shfl_xor_sync(0xffffffffu, s, o);
    float mu = s * (1.0f / 64.0f);
    float t0 = a0 - mu, t1 = a1 - mu;
    float ss = t0 * t0 + t1 * t1;
    #pragma unroll
    for (int o = 16; o; o >>= 1) ss += __shfl_xor_sync(0xffffffffu, ss, o);
    float r = rsqrtf(ss * (1.0f / 64.0f) + 1e-5f) * scale;
    a0 = t0 * r; a1 = t1 * r;
}

__global__ void __launch_bounds__(256) qkv_ln_kernel(
    const float* __restrict__ x,
    const float* __restrict__ Wq,
    const float* __restrict__ Wk,
    const float* __restrict__ Wv)
{
    __shared__ float sW[3 * D_ * I_];   // 28416 B
    __shared__ float sx[D_ * 64];       // 9472 B
    int tid = threadIdx.x;
    int b  = blockIdx.x >> 6;
    int f0 = (blockIdx.x & 63) << 6;

    if (tid < 64) g_c[b * F_ + f0 + tid] = 0.0f;   // zero colsum accumulator

    for (int i = tid; i < D_ * I_; i += 256) {
        sW[i]               = Wq[i];
        sW[D_ * I_ + i]     = Wk[i];
        sW[2 * D_ * I_ + i] = Wv[i];
    }
    for (int i = tid; i < D_ * 64; i += 256) {
        int d = i >> 6, c = i & 63;
        sx[i] = x[(size_t)b * D_ * F_ + (size_t)d * F_ + f0 + c];
    }
    __syncthreads();

    int warp = tid >> 5, lane = tid & 31;
    int fbase = warp * 8;

    float acc[8][6] = {};
    #pragma unroll
    for (int dc = 0; dc < 40; dc += 4) {
        float wr[4][6];
        #pragma unroll
        for (int dd = 0; dd < 4; ++dd) {
            int d = dc + dd;
            if (d < D_) {
                const float* w = sW + d * I_;
                wr[dd][0] = w[lane];                 wr[dd][1] = w[lane + 32];
                wr[dd][2] = w[D_ * I_ + lane];       wr[dd][3] = w[D_ * I_ + lane + 32];
                wr[dd][4] = w[2 * D_ * I_ + lane];   wr[dd][5] = w[2 * D_ * I_ + lane + 32];
            } else {
                #pragma unroll
                for (int u = 0; u < 6; ++u) wr[dd][u] = 0.0f;
            }
        }
        #pragma unroll
        for (int j = 0; j < 8; ++j) {
            #pragma unroll
            for (int dd = 0; dd < 4; ++dd) {
                int d = dc + dd;
                float xd = (d < D_) ? sx[d * 64 + fbase + j] : 0.0f;
                acc[j][0] += xd * wr[dd][0];
                acc[j][1] += xd * wr[dd][1];
                acc[j][2] += xd * wr[dd][2];
                acc[j][3] += xd * wr[dd][3];
                acc[j][4] += xd * wr[dd][4];
                acc[j][5] += xd * wr[dd][5];
            }
        }
    }

    #pragma unroll
    for (int j = 0; j < 8; ++j) {
        ln64(acc[j][0], acc[j][1], 0.18033688f);   // 0.125 * log2(e)
        ln64(acc[j][2], acc[j][3], 1.0f);
        ln64(acc[j][4], acc[j][5], 1.0f);
        size_t ov = ((size_t)b * F_ + f0 + fbase + j) * I_ + lane;
        g_qh[ov] = __float2half_rn(acc[j][0]); g_qh[ov + 32] = __float2half_rn(acc[j][1]);
        g_kh[ov] = __float2half_rn(acc[j][2]); g_kh[ov + 32] = __float2half_rn(acc[j][3]);
        g_v [ov] = acc[j][4];                  g_v [ov + 32] = acc[j][5];
    }
}

// ---------------------------------------------------------------------------
// Kernel 2: S[m][n] = q[m]·k[n] via fp16 mma.sync; P = 2^S (ex2).
// 128 thr (4 warps, 2x2), CTA tile 128m x 64n, warp tile 64m x 32n, K=64.
// Small CTA -> 3-4 CTAs/SM so one CTA's MUFU/store epilogue overlaps
// another's tensor phase. P staged in smem (reusing operand area) and
// written as coalesced 128B rows. Column sums via shfl+smem+global atomics.
// ---------------------------------------------------------------------------
#define QK_SA   0u
#define QK_SB   16384u
#define QK_SCOL 24576
#define QK_SMEM (24576 + 256)

__global__ void __launch_bounds__(128) qk_hmma_kernel() {
    extern __shared__ char sm[];
    unsigned sb = smem_u32(sm);
    float* scol = (float*)(sm + QK_SCOL);

    int tid = threadIdx.x, lane = tid & 31, w = tid >> 5;
    int m0 = blockIdx.x * 128, n0 = blockIdx.y * 64, b = blockIdx.z;

    const __half* qv = g_qh + ((size_t)b * F_ + m0) * I_;
    const __half* kv = g_kh + ((size_t)b * F_ + n0) * I_;

    if (tid < 64) scol[tid] = 0.0f;

    // loads: q 128 rows x 128B (8 per thread), k 64 rows x 128B (4 per thread)
    int r = tid >> 3, c16 = tid & 7;
    #pragma unroll
    for (int j = 0; j < 8; ++j) {
        int row = r + j * 16;
        cp_async16(sb + QK_SA + SW128B((unsigned)(row * 128 + c16 * 16)),
                   qv + (size_t)row * I_ + c16 * 8);
    }
    #pragma unroll
    for (int j = 0; j < 4; ++j) {
        int row = r + j * 16;
        cp_async16(sb + QK_SB + SW128B((unsigned)(row * 128 + c16 * 16)),
                   kv + (size_t)row * I_ + c16 * 8);
    }
    cp_commit();
    cp_wait<0>();
    __syncthreads();

    int wm = w & 1, wn = w >> 1;             // 2 x 2 warp grid
    unsigned a_lrow = (unsigned)((lane & 7) + ((lane >> 3) & 1) * 8);
    unsigned a_koff = (unsigned)((lane >> 4) << 4);
    unsigned b_lrow = (unsigned)((lane & 7) + ((lane >> 4) << 3));
    unsigned b_koff = (unsigned)(((lane >> 3) & 1) << 4);

    float acc[4][4][4] = {};

    #pragma unroll
    for (int ks = 0; ks < 4; ++ks) {
        unsigned a[4][4], bB[2][4];
        #pragma unroll
        for (int mf = 0; mf < 4; ++mf) {
            unsigned row = (unsigned)(wm * 64 + mf * 16) + a_lrow;
            ldm_x4(a[mf], sb + QK_SA + SW128B(row * 128 + a_koff + ks * 32));
        }
        #pragma unroll
        for (int np = 0; np < 2; ++np) {
            unsigned row = (unsigned)(wn * 32 + np * 16) + b_lrow;
            ldm_x4(bB[np], sb + QK_SB + SW128B(row * 128 + b_koff + ks * 32));
        }
        #pragma unroll
        for (int mf = 0; mf < 4; ++mf)
            #pragma unroll
            for (int nf = 0; nf < 4; ++nf) {
                int np = nf >> 1, s = nf & 1;
                mma_f16(acc[mf][nf], a[mf], bB[np][2 * s], bB[np][2 * s + 1]);
            }
    }

    // ---- epilogue: ex2 + colsums; stage P tile (128 x 64 halves = 128B rows)
    //      in the operand smem area; then coalesced global writes ----
    __syncthreads();   // all warps done reading q/k smem

    int r0 = lane >> 2, c2 = (lane & 3) * 2;
    float cp0[4] = {}, cp1[4] = {};
    #pragma unroll
    for (int mf = 0; mf < 4; ++mf) {
        int rml = wm * 64 + mf * 16 + r0;       // local m row (0..127)
        #pragma unroll
        for (int nf = 0; nf < 4; ++nf) {
            int cnl = wn * 32 + nf * 8 + c2;    // local n col (0..63)
            float e0 = ex2(acc[mf][nf][0]);
            float e1 = ex2(acc[mf][nf][1]);
            float e2 = ex2(acc[mf][nf][2]);
            float e3 = ex2(acc[mf][nf][3]);
            cp0[nf] += e0 + e2;
            cp1[nf] += e1 + e3;
            unsigned o1 = (unsigned)(rml * 128 + cnl * 2);
            unsigned o2 = (unsigned)((rml + 8) * 128 + cnl * 2);
            *(__half2*)(sm + SW128B(o1)) = __floats2half2_rn(e0, e1);
            *(__half2*)(sm + SW128B(o2)) = __floats2half2_rn(e2, e3);
        }
    }
    #pragma unroll
    for (int o = 4; o <= 16; o <<= 1)
        #pragma unroll
        for (int nf = 0; nf < 4; ++nf) {
            cp0[nf] += __shfl_xor_sync(0xffffffffu, cp0[nf], o);
            cp1[nf] += __shfl_xor_sync(0xffffffffu, cp1[nf], o);
        }
    if (lane < 4) {
        #pragma unroll
        for (int nf = 0; nf < 4; ++nf) {
            atomicAdd(&scol[wn * 32 + nf * 8 + lane * 2],     cp0[nf]);
            atomicAdd(&scol[wn * 32 + nf * 8 + lane * 2 + 1], cp1[nf]);
        }
    }
    __syncthreads();

    __half* Pp = g_P + ((size_t)b << 24);
    #pragma unroll
    for (int i2 = 0; i2 < 8; ++i2) {
        int idx = tid + i2 * 128;
        int rr = idx >> 3, cc = idx & 7;
        uint4 val = *(uint4*)(sm + SW128B((unsigned)(rr * 128 + cc * 16)));
        *(uint4*)(Pp + (size_t)(m0 + rr) * F_ + n0 + cc * 8) = val;
    }
    if (tid < 64) atomicAdd(&g_c[b * F_ + n0 + tid], scol[tid]);
}

// ---------------------------------------------------------------------------
// Kernel 3: g_vs[b][n][i] = fp16( v[b][n][i] / c[b][n] ). 8 elems/thread.
// ---------------------------------------------------------------------------
__global__ void __launch_bounds__(256) vscale_kernel() {
    size_t e = ((size_t)blockIdx.x * 256 + threadIdx.x) * 8;
    int row = (int)(e >> 6);             // b*F + n
    float rc = 1.0f / g_c[row];

    const float* vp = g_v + e;
    float4 v0 = *(const float4*)vp;
    float4 v1 = *(const float4*)(vp + 4);

    __half2 h[4];
    h[0] = __floats2half2_rn(v0.x * rc, v0.y * rc);
    h[1] = __floats2half2_rn(v0.z * rc, v0.w * rc);
    h[2] = __floats2half2_rn(v1.x * rc, v1.y * rc);
    h[3] = __floats2half2_rn(v1.z * rc, v1.w * rc);
    *(uint4*)(g_vs + e) = *(uint4*)h;
}

// ---------------------------------------------------------------------------
// Kernel 4: out[m][i] = sum_n P[m][n] * Vs[n][i]  via fp16 mma.sync.
// 128 thr, 4 warps, CTA tile 256(m) x 64(i), warp tile 64m x 64i.
// K=4096 in 64 chunks of 64; 2-stage ping-pong (80 KB -> 2 CTA/SM).
// ---------------------------------------------------------------------------
#define AV_PST   32768u
#define AV_VBASE 65536u
#define AV_VST   8192u
#define AV_SMEM  81920

__device__ __forceinline__ void av_issue(unsigned sb, int u, int m0,
                                         const __half* Pb, const __half* Vb,
                                         int tid) {
    unsigned pd = sb + (unsigned)(u & 1) * AV_PST;
    unsigned vd = sb + AV_VBASE + (unsigned)(u & 1) * AV_VST;
    int kc = u * 64;
    int r = tid >> 3, c16 = tid & 7;
    #pragma unroll
    for (int j = 0; j < 16; ++j) {
        int row = r + j * 16;
        cp_async16(pd + SW128B((unsigned)(row * 128 + c16 * 16)),
                   Pb + (size_t)(m0 + row) * F_ + kc + c16 * 8);
    }
    #pragma unroll
    for (int j = 0; j < 4; ++j) {
        int row = r + j * 16;
        cp_async16(vd + SW128B((unsigned)(row * 128 + c16 * 16)),
                   Vb + (size_t)(kc + row) * I_ + c16 * 8);
    }
    cp_commit();
}

__global__ void __launch_bounds__(128) av_hmma_kernel(float* __restrict__ out) {
    extern __shared__ char sm[];
    unsigned sb = smem_u32(sm);

    int tid = threadIdx.x, lane = tid & 31, w = tid >> 5;
    int m0 = blockIdx.x * 256;
    int b  = blockIdx.y;

    const __half* Pb = g_P  + ((size_t)b << 24);
    const __half* Vb = g_vs + (size_t)b * F_ * I_;

    float acc[4][8][4] = {};

    av_issue(sb, 0, m0, Pb, Vb, tid);
    av_issue(sb, 1, m0, Pb, Vb, tid);

    unsigned a_base = (unsigned)((w * 64 + (lane & 15)) * 128 + ((lane >> 4) << 4));
    unsigned b_base = (unsigned)((lane & 15) * 128 + ((lane >> 4) << 4));

    for (int t = 0; t < F_ / 64; ++t) {
        if (t + 1 < F_ / 64) cp_wait<1>();
        else                 cp_wait<0>();
        __syncthreads();                      // buffer t ready for all warps

        unsigned pbuf = sb + (unsigned)(t & 1) * AV_PST;
        unsigned vbuf = sb + AV_VBASE + (unsigned)(t & 1) * AV_VST;

        #pragma unroll
        for (int s = 0; s < 4; ++s) {
            unsigned a[4][4], bv[4][4];
            #pragma unroll
            for (int mf = 0; mf < 4; ++mf)
                ldm_x4(a[mf], pbuf + SW128B(a_base + mf * 2048 + s * 32));
            #pragma unroll
            for (int p = 0; p < 4; ++p)
                ldm_x4_t(bv[p], vbuf + SW128B(b_base + s * 2048 + p * 32));

            #pragma unroll
            for (int mf = 0; mf < 4; ++mf)
                #pragma unroll
                for (int p = 0; p < 4; ++p) {
                    mma_f16(acc[mf][2 * p],     a[mf], bv[p][0], bv[p][1]);
                    mma_f16(acc[mf][2 * p + 1], a[mf], bv[p][2], bv[p][3]);
                }
        }
        __syncthreads();                      // all warps done reading buffer t
        if (t + 2 < F_ / 64)
            av_issue(sb, t + 2, m0, Pb, Vb, tid);
    }

    int r0 = lane >> 2, c2 = (lane & 3) * 2;
    #pragma unroll
    for (int mf = 0; mf < 4; ++mf) {
        int mrow = m0 + w * 64 + mf * 16 + r0;
        float* o0 = out + ((size_t)b * F_ + mrow) * I_ + c2;
        float* o1 = o0 + 8 * I_;
        #pragma unroll
        for (int it = 0; it < 8; ++it) {
            *(float2*)(o0 + it * 8) = make_float2(acc[mf][it][0], acc[mf][it][1]);
            *(float2*)(o1 + it * 8) = make_float2(acc[mf][it][2], acc[mf][it][3]);
        }
    }
}

// ---------------------------------------------------------------------------
extern "C" void kernel_launch(void* const* d_in, const int* in_sizes, int n_in,
                              void* d_out, int out_size)
{
    const float* x  = (const float*)d_in[0];
    const float* Wq = (const float*)d_in[1];
    const float* Wk = (const float*)d_in[2];
    const float* Wv = (const float*)d_in[3];
    float* out = (float*)d_out;

    static bool attr_done = false;
    if (!attr_done) {
        cudaFuncSetAttribute(qk_hmma_kernel,
                             cudaFuncAttributeMaxDynamicSharedMemorySize, QK_SMEM);
        cudaFuncSetAttribute(av_hmma_kernel,
                             cudaFuncAttributeMaxDynamicSharedMemorySize, AV_SMEM);
        attr_done = true;
    }

    qkv_ln_kernel<<<B_ * F_ / 64, 256>>>(x, Wq, Wk, Wv);
    qk_hmma_kernel<<<dim3(F_ / 128, F_ / 64, B_), 128, QK_SMEM>>>();
    vscale_kernel<<<B_ * F_ * I_ / (256 * 8), 256>>>();
    av_hmma_kernel<<<dim3(F_ / 256, B_), 128, AV_SMEM>>>(out);
}

// round 11
// speedup vs baseline: 5.6898x; 1.0084x over previous
#include <cuda_runtime.h>
#include <cuda_fp16.h>
#include <cstdint>
#include <math.h>

#define B_ 16
#define D_ 37
#define F_ 4096
#define I_ 64

// ---- scratch (static device globals: allocation-free) ----
__device__ __half g_qh[B_ * F_ * I_];                // [b][f][i], LN'd, *0.125*log2e, fp16
__device__ __half g_kh[B_ * F_ * I_];                // [b][f][i], LN'd, fp16
__device__ float  g_v [B_ * F_ * I_];                // [b][f][i], LN'd fp32
__device__ float  g_c [B_ * F_];                     // c[n] = sum_m 2^(S[m][n])
__device__ __half g_P [(size_t)B_ * F_ * F_];        // P[b][m][n] = 2^S, fp16, n contig
__device__ __half g_vs[B_ * F_ * I_];                // Vs[b][n][i] = v[n][i]/c[n], fp16

#define SW128B(o) ((o) ^ (((o) >> 3) & 0x70))

// ======================= PTX helpers (arch-generic, sm_80+) ==================
__device__ __forceinline__ unsigned smem_u32(const void* p) {
    unsigned a;
    asm("{ .reg .u64 t; cvta.to.shared.u64 t, %1; cvt.u32.u64 %0, t; }"
        : "=r"(a) : "l"(p));
    return a;
}
__device__ __forceinline__ void cp_async16(unsigned dst, const void* src) {
    asm volatile("cp.async.cg.shared.global [%0], [%1], 16;" :: "r"(dst), "l"(src));
}
__device__ __forceinline__ void cp_commit() {
    asm volatile("cp.async.commit_group;" ::: "memory");
}
template <int N>
__device__ __forceinline__ void cp_wait() {
    asm volatile("cp.async.wait_group %0;" :: "n"(N) : "memory");
}
__device__ __forceinline__ void ldm_x4(unsigned* r, unsigned addr) {
    asm volatile("ldmatrix.sync.aligned.m8n8.x4.shared.b16 {%0,%1,%2,%3}, [%4];"
                 : "=r"(r[0]), "=r"(r[1]), "=r"(r[2]), "=r"(r[3]) : "r"(addr));
}
__device__ __forceinline__ void ldm_x4_t(unsigned* r, unsigned addr) {
    asm volatile("ldmatrix.sync.aligned.m8n8.x4.trans.shared.b16 {%0,%1,%2,%3}, [%4];"
                 : "=r"(r[0]), "=r"(r[1]), "=r"(r[2]), "=r"(r[3]) : "r"(addr));
}
__device__ __forceinline__ void mma_f16(float* c, const unsigned* a,
                                        unsigned b0, unsigned b1) {
    asm volatile(
        "mma.sync.aligned.m16n8k16.row.col.f32.f16.f16.f32 "
        "{%0,%1,%2,%3}, {%4,%5,%6,%7}, {%8,%9}, {%0,%1,%2,%3};"
        : "+f"(c[0]), "+f"(c[1]), "+f"(c[2]), "+f"(c[3])
        : "r"(a[0]), "r"(a[1]), "r"(a[2]), "r"(a[3]), "r"(b0), "r"(b1));
}
// pack (lo, hi) -> half2 and take 2^x elementwise in fp16
__device__ __forceinline__ unsigned ex2_h2(float hi, float lo) {
    unsigned p, o;
    asm("cvt.rn.f16x2.f32 %0, %1, %2;" : "=r"(p) : "f"(hi), "f"(lo));
    asm("ex2.approx.f16x2 %0, %1;" : "=r"(o) : "r"(p));
    return o;
}

// ---------------------------------------------------------------------------
// Kernel 1: q/k/v = LN(x^T @ W). Block = 64 consecutive f. Also zeroes g_c.
// q scaled by 0.125*log2(e) so qk epilogue can use raw ex2.
// ---------------------------------------------------------------------------
__device__ __forceinline__ void ln64(float& a0, float& a1, float scale) {
    float s = a0 + a1;
    #pragma unroll
    for (int o = 16; o; o >>= 1) s += __shfl_xor_sync(0xffffffffu, s, o);
    float mu = s * (1.0f / 64.0f);
    float t0 = a0 - mu, t1 = a1 - mu;
    float ss = t0 * t0 + t1 * t1;
    #pragma unroll
    for (int o = 16; o; o >>= 1) ss += __shfl_xor_sync(0xffffffffu, ss, o);
    float r = rsqrtf(ss * (1.0f / 64.0f) + 1e-5f) * scale;
    a0 = t0 * r; a1 = t1 * r;
}

__global__ void __launch_bounds__(256) qkv_ln_kernel(
    const float* __restrict__ x,
    const float* __restrict__ Wq,
    const float* __restrict__ Wk,
    const float* __restrict__ Wv)
{
    __shared__ float sW[3 * D_ * I_];   // 28416 B
    __shared__ float sx[D_ * 64];       // 9472 B
    int tid = threadIdx.x;
    int b  = blockIdx.x >> 6;
    int f0 = (blockIdx.x & 63) << 6;

    if (tid < 64) g_c[b * F_ + f0 + tid] = 0.0f;   // zero colsum accumulator

    for (int i = tid; i < D_ * I_; i += 256) {
        sW[i]               = Wq[i];
        sW[D_ * I_ + i]     = Wk[i];
        sW[2 * D_ * I_ + i] = Wv[i];
    }
    for (int i = tid; i < D_ * 64; i += 256) {
        int d = i >> 6, c = i & 63;
        sx[i] = x[(size_t)b * D_ * F_ + (size_t)d * F_ + f0 + c];
    }
    __syncthreads();

    int warp = tid >> 5, lane = tid & 31;
    int fbase = warp * 8;

    float acc[8][6] = {};
    #pragma unroll
    for (int dc = 0; dc < 40; dc += 4) {
        float wr[4][6];
        #pragma unroll
        for (int dd = 0; dd < 4; ++dd) {
            int d = dc + dd;
            if (d < D_) {
                const float* w = sW + d * I_;
                wr[dd][0] = w[lane];                 wr[dd][1] = w[lane + 32];
                wr[dd][2] = w[D_ * I_ + lane];       wr[dd][3] = w[D_ * I_ + lane + 32];
                wr[dd][4] = w[2 * D_ * I_ + lane];   wr[dd][5] = w[2 * D_ * I_ + lane + 32];
            } else {
                #pragma unroll
                for (int u = 0; u < 6; ++u) wr[dd][u] = 0.0f;
            }
        }
        #pragma unroll
        for (int j = 0; j < 8; ++j) {
            #pragma unroll
            for (int dd = 0; dd < 4; ++dd) {
                int d = dc + dd;
                float xd = (d < D_) ? sx[d * 64 + fbase + j] : 0.0f;
                acc[j][0] += xd * wr[dd][0];
                acc[j][1] += xd * wr[dd][1];
                acc[j][2] += xd * wr[dd][2];
                acc[j][3] += xd * wr[dd][3];
                acc[j][4] += xd * wr[dd][4];
                acc[j][5] += xd * wr[dd][5];
            }
        }
    }

    #pragma unroll
    for (int j = 0; j < 8; ++j) {
        ln64(acc[j][0], acc[j][1], 0.18033688f);   // 0.125 * log2(e)
        ln64(acc[j][2], acc[j][3], 1.0f);
        ln64(acc[j][4], acc[j][5], 1.0f);
        size_t ov = ((size_t)b * F_ + f0 + fbase + j) * I_ + lane;
        g_qh[ov] = __float2half_rn(acc[j][0]); g_qh[ov + 32] = __float2half_rn(acc[j][1]);
        g_kh[ov] = __float2half_rn(acc[j][2]); g_kh[ov + 32] = __float2half_rn(acc[j][3]);
        g_v [ov] = acc[j][4];                  g_v [ov + 32] = acc[j][5];
    }
}

// ---------------------------------------------------------------------------
// Kernel 2: S[m][n] = q[m]·k[n] via fp16 mma.sync; P = 2^S via ex2.f16x2.
// 128 thr (4 warps), CTA tile 128m x 64n; warp w owns m rows [32w, 32w+32),
// ALL 64 n. Epilogue is warp-private: each warp ex2-packs, stages its own
// rows in a dedicated smem region, and stores them — NO CTA-wide sync after
// the operand load, so one warp's MUFU phase overlaps others' HMMA phase.
// Column sums: fp32 warp shfl-reduce + direct global atomics.
// ---------------------------------------------------------------------------
#define QK_SA   0u
#define QK_SB   16384u
#define QK_PS   24576u
#define QK_SMEM (24576 + 16384)

__global__ void __launch_bounds__(128) qk_hmma_kernel() {
    extern __shared__ char sm[];
    unsigned sb = smem_u32(sm);

    int tid = threadIdx.x, lane = tid & 31, w = tid >> 5;
    int m0 = blockIdx.x * 128, n0 = blockIdx.y * 64, b = blockIdx.z;

    const __half* qv = g_qh + ((size_t)b * F_ + m0) * I_;
    const __half* kv = g_kh + ((size_t)b * F_ + n0) * I_;

    // loads: q 128 rows x 128B (8 per thread), k 64 rows x 128B (4 per thread)
    int r = tid >> 3, c16 = tid & 7;
    #pragma unroll
    for (int j = 0; j < 8; ++j) {
        int row = r + j * 16;
        cp_async16(sb + QK_SA + SW128B((unsigned)(row * 128 + c16 * 16)),
                   qv + (size_t)row * I_ + c16 * 8);
    }
    #pragma unroll
    for (int j = 0; j < 4; ++j) {
        int row = r + j * 16;
        cp_async16(sb + QK_SB + SW128B((unsigned)(row * 128 + c16 * 16)),
                   kv + (size_t)row * I_ + c16 * 8);
    }
    cp_commit();
    cp_wait<0>();
    __syncthreads();               // the ONLY CTA-wide sync in this kernel

    unsigned a_lrow = (unsigned)((lane & 7) + ((lane >> 3) & 1) * 8);
    unsigned a_koff = (unsigned)((lane >> 4) << 4);
    unsigned b_lrow = (unsigned)((lane & 7) + ((lane >> 4) << 3));
    unsigned b_koff = (unsigned)(((lane >> 3) & 1) << 4);

    float acc[2][8][4] = {};       // mf (16m) x nf (8n) x frag

    #pragma unroll
    for (int ks = 0; ks < 4; ++ks) {
        unsigned a[2][4], bB[4][4];
        #pragma unroll
        for (int mf = 0; mf < 2; ++mf) {
            unsigned row = (unsigned)(w * 32 + mf * 16) + a_lrow;
            ldm_x4(a[mf], sb + QK_SA + SW128B(row * 128 + a_koff + ks * 32));
        }
        #pragma unroll
        for (int np = 0; np < 4; ++np) {
            unsigned row = (unsigned)(np * 16) + b_lrow;
            ldm_x4(bB[np], sb + QK_SB + SW128B(row * 128 + b_koff + ks * 32));
        }
        #pragma unroll
        for (int mf = 0; mf < 2; ++mf)
            #pragma unroll
            for (int nf = 0; nf < 8; ++nf) {
                int np = nf >> 1, s = nf & 1;
                mma_f16(acc[mf][nf], a[mf], bB[np][2 * s], bB[np][2 * s + 1]);
            }
    }

    // ---- warp-private epilogue: ex2.f16x2, fp32 colsums, stage own rows ----
    int r0 = lane >> 2, c2 = (lane & 3) * 2;
    float cpA[8] = {}, cpB[8] = {};
    #pragma unroll
    for (int mf = 0; mf < 2; ++mf) {
        int rml = w * 32 + mf * 16 + r0;
        #pragma unroll
        for (int nf = 0; nf < 8; ++nf) {
            int cnl = nf * 8 + c2;
            unsigned p01 = ex2_h2(acc[mf][nf][1], acc[mf][nf][0]);  // row rml
            unsigned p23 = ex2_h2(acc[mf][nf][3], acc[mf][nf][2]);  // row rml+8
            __half2 h01 = *(__half2*)&p01;
            __half2 h23 = *(__half2*)&p23;
            cpA[nf] += __low2float(h01)  + __low2float(h23);
            cpB[nf] += __high2float(h01) + __high2float(h23);
            *(unsigned*)(sm + QK_PS + SW128B((unsigned)(rml * 128 + cnl * 2)))       = p01;
            *(unsigned*)(sm + QK_PS + SW128B((unsigned)((rml + 8) * 128 + cnl * 2))) = p23;
        }
    }
    __syncwarp();

    #pragma unroll
    for (int o = 4; o <= 16; o <<= 1)
        #pragma unroll
        for (int nf = 0; nf < 8; ++nf) {
            cpA[nf] += __shfl_xor_sync(0xffffffffu, cpA[nf], o);
            cpB[nf] += __shfl_xor_sync(0xffffffffu, cpB[nf], o);
        }
    if (lane < 4) {
        #pragma unroll
        for (int nf = 0; nf < 8; ++nf) {
            atomicAdd(&g_c[b * F_ + n0 + nf * 8 + lane * 2],     cpA[nf]);
            atomicAdd(&g_c[b * F_ + n0 + nf * 8 + lane * 2 + 1], cpB[nf]);
        }
    }

    // per-warp coalesced P store (own 32 rows x 128B)
    __half* Pp = g_P + ((size_t)b << 24);
    #pragma unroll
    for (int i = 0; i < 8; ++i) {
        int idx = lane + i * 32;
        int rr = w * 32 + (idx >> 3), cc = idx & 7;
        uint4 val = *(uint4*)(sm + QK_PS + SW128B((unsigned)(rr * 128 + cc * 16)));
        *(uint4*)(Pp + (size_t)(m0 + rr) * F_ + n0 + cc * 8) = val;
    }
}

// ---------------------------------------------------------------------------
// Kernel 3: g_vs[b][n][i] = fp16( v[b][n][i] / c[b][n] ). 8 elems/thread.
// ---------------------------------------------------------------------------
__global__ void __launch_bounds__(256) vscale_kernel() {
    size_t e = ((size_t)blockIdx.x * 256 + threadIdx.x) * 8;
    int row = (int)(e >> 6);             // b*F + n
    float rc = 1.0f / g_c[row];

    const float* vp = g_v + e;
    float4 v0 = *(const float4*)vp;
    float4 v1 = *(const float4*)(vp + 4);

    __half2 h[4];
    h[0] = __floats2half2_rn(v0.x * rc, v0.y * rc);
    h[1] = __floats2half2_rn(v0.z * rc, v0.w * rc);
    h[2] = __floats2half2_rn(v1.x * rc, v1.y * rc);
    h[3] = __floats2half2_rn(v1.z * rc, v1.w * rc);
    *(uint4*)(g_vs + e) = *(uint4*)h;
}

// ---------------------------------------------------------------------------
// Kernel 4: out[m][i] = sum_n P[m][n] * Vs[n][i]  via fp16 mma.sync.
// 128 thr, 4 warps, CTA tile 256(m) x 64(i), warp tile 64m x 64i.
// K=4096 in 64 chunks of 64; 2-stage ping-pong (80 KB -> 2 CTA/SM).
// ---------------------------------------------------------------------------
#define AV_PST   32768u
#define AV_VBASE 65536u
#define AV_VST   8192u
#define AV_SMEM  81920

__device__ __forceinline__ void av_issue(unsigned sb, int u, int m0,
                                         const __half* Pb, const __half* Vb,
                                         int tid) {
    unsigned pd = sb + (unsigned)(u & 1) * AV_PST;
    unsigned vd = sb + AV_VBASE + (unsigned)(u & 1) * AV_VST;
    int kc = u * 64;
    int r = tid >> 3, c16 = tid & 7;
    #pragma unroll
    for (int j = 0; j < 16; ++j) {
        int row = r + j * 16;
        cp_async16(pd + SW128B((unsigned)(row * 128 + c16 * 16)),
                   Pb + (size_t)(m0 + row) * F_ + kc + c16 * 8);
    }
    #pragma unroll
    for (int j = 0; j < 4; ++j) {
        int row = r + j * 16;
        cp_async16(vd + SW128B((unsigned)(row * 128 + c16 * 16)),
                   Vb + (size_t)(kc + row) * I_ + c16 * 8);
    }
    cp_commit();
}

__global__ void __launch_bounds__(128) av_hmma_kernel(float* __restrict__ out) {
    extern __shared__ char sm[];
    unsigned sb = smem_u32(sm);

    int tid = threadIdx.x, lane = tid & 31, w = tid >> 5;
    int m0 = blockIdx.x * 256;
    int b  = blockIdx.y;

    const __half* Pb = g_P  + ((size_t)b << 24);
    const __half* Vb = g_vs + (size_t)b * F_ * I_;

    float acc[4][8][4] = {};

    av_issue(sb, 0, m0, Pb, Vb, tid);
    av_issue(sb, 1, m0, Pb, Vb, tid);

    unsigned a_base = (unsigned)((w * 64 + (lane & 15)) * 128 + ((lane >> 4) << 4));
    unsigned b_base = (unsigned)((lane & 15) * 128 + ((lane >> 4) << 4));

    for (int t = 0; t < F_ / 64; ++t) {
        if (t + 1 < F_ / 64) cp_wait<1>();
        else                 cp_wait<0>();
        __syncthreads();                      // buffer t ready for all warps

        unsigned pbuf = sb + (unsigned)(t & 1) * AV_PST;
        unsigned vbuf = sb + AV_VBASE + (unsigned)(t & 1) * AV_VST;

        #pragma unroll
        for (int s = 0; s < 4; ++s) {
            unsigned a[4][4], bv[4][4];
            #pragma unroll
            for (int mf = 0; mf < 4; ++mf)
                ldm_x4(a[mf], pbuf + SW128B(a_base + mf * 2048 + s * 32));
            #pragma unroll
            for (int p = 0; p < 4; ++p)
                ldm_x4_t(bv[p], vbuf + SW128B(b_base + s * 2048 + p * 32));

            #pragma unroll
            for (int mf = 0; mf < 4; ++mf)
                #pragma unroll
                for (int p = 0; p < 4; ++p) {
                    mma_f16(acc[mf][2 * p],     a[mf], bv[p][0], bv[p][1]);
                    mma_f16(acc[mf][2 * p + 1], a[mf], bv[p][2], bv[p][3]);
                }
        }
        __syncthreads();                      // all warps done reading buffer t
        if (t + 2 < F_ / 64)
            av_issue(sb, t + 2, m0, Pb, Vb, tid);
    }

    int r0 = lane >> 2, c2 = (lane & 3) * 2;
    #pragma unroll
    for (int mf = 0; mf < 4; ++mf) {
        int mrow = m0 + w * 64 + mf * 16 + r0;
        float* o0 = out + ((size_t)b * F_ + mrow) * I_ + c2;
        float* o1 = o0 + 8 * I_;
        #pragma unroll
        for (int it = 0; it < 8; ++it) {
            *(float2*)(o0 + it * 8) = make_float2(acc[mf][it][0], acc[mf][it][1]);
            *(float2*)(o1 + it * 8) = make_float2(acc[mf][it][2], acc[mf][it][3]);
        }
    }
}

// ---------------------------------------------------------------------------
extern "C" void kernel_launch(void* const* d_in, const int* in_sizes, int n_in,
                              void* d_out, int out_size)
{
    const float* x  = (const float*)d_in[0];
    const float* Wq = (const float*)d_in[1];
    const float* Wk = (const float*)d_in[2];
    const float* Wv = (const float*)d_in[3];
    float* out = (float*)d_out;

    static bool attr_done = false;
    if (!attr_done) {
        cudaFuncSetAttribute(qk_hmma_kernel,
                             cudaFuncAttributeMaxDynamicSharedMemorySize, QK_SMEM);
        cudaFuncSetAttribute(av_hmma_kernel,
                             cudaFuncAttributeMaxDynamicSharedMemorySize, AV_SMEM);
        attr_done = true;
    }

    qkv_ln_kernel<<<B_ * F_ / 64, 256>>>(x, Wq, Wk, Wv);
    qk_hmma_kernel<<<dim3(F_ / 128, F_ / 64, B_), 128, QK_SMEM>>>();
    vscale_kernel<<<B_ * F_ * I_ / (256 * 8), 256>>>();
    av_hmma_kernel<<<dim3(F_ / 256, B_), 128, AV_SMEM>>>(out);
}